// round 12
// baseline (speedup 1.0000x reference)
#include <cuda_runtime.h>
#include <cuda_fp16.h>
#include <math.h>
#include <stdint.h>

// Problem constants
#define Bn 4
#define Tn 2048
#define Dn 1024
#define Hn 16
#define HS 64
#define Mrows (Bn*Tn)          // 8192

// Scratch (device globals; no runtime allocation allowed)
__device__ __half g_q [(size_t)Bn*Hn*Tn*HS];   // [B,H,T,64] rope'd+scaled fp16
__device__ __half g_k [(size_t)Bn*Hn*Tn*HS];   // [B,H,T,64] rope'd fp16
__device__ __half g_vt[(size_t)Bn*Hn*HS*Tn];   // [B,H,64,T] V TRANSPOSED fp16
__device__ __half g_ao[(size_t)Mrows*Dn];      // attn out, packed fp16 A-tiles
__device__ float2 g_rope[Tn*32];               // (cos, sin) table
// fragment-major packed fp16 operands: [rowblk][ktile(32-k)][4096 halves]
__device__ __half g_xt[(size_t)Mrows*Dn];
__device__ __half g_wk[(size_t)3*Dn*Dn];
__device__ __half g_wp[(size_t)Dn*Dn];

// ---------------------------------------------------------------------------
// helpers
// ---------------------------------------------------------------------------
__device__ __forceinline__ float ex2(float x) {
    float y;
    asm("ex2.approx.f32 %0, %1;" : "=f"(y) : "f"(x));
    return y;
}

// fp16 mma: D(f32) += A(f16 m16k16) * B(f16 k16n8)
__device__ __forceinline__ void mma_f16(float c[4],
                                        uint32_t a0, uint32_t a1, uint32_t a2, uint32_t a3,
                                        uint32_t b0, uint32_t b1)
{
    asm volatile(
        "mma.sync.aligned.m16n8k16.row.col.f32.f16.f16.f32 "
        "{%0,%1,%2,%3}, {%4,%5,%6,%7}, {%8,%9}, {%0,%1,%2,%3};\n"
        : "+f"(c[0]), "+f"(c[1]), "+f"(c[2]), "+f"(c[3])
        : "r"(a0), "r"(a1), "r"(a2), "r"(a3), "r"(b0), "r"(b1));
}

__device__ __forceinline__ void cpa16(uint32_t dst_smem, const void* src) {
    asm volatile("cp.async.cg.shared.global [%0], [%1], 16;" :: "r"(dst_smem), "l"(src));
}
#define CP_COMMIT()  asm volatile("cp.async.commit_group;")
#define CP_WAIT(n)   asm volatile("cp.async.wait_group " #n ";")

// word (32-bit = 2 halves) offset within a 128x32 fp16 tile (2048 words)
// p = k-pair index 0..15 (k = 2p)
__device__ __forceinline__ int offA_h(int m, int p) {
    return (((((m >> 4) * 2 + (p >> 3)) * 8 + (m & 7)) * 4 + (p & 3)) * 4)
           + ((p >> 2) & 1) * 2 + ((m >> 3) & 1);
}
__device__ __forceinline__ int offB_h(int n, int p) {
    return (((((n >> 3) * 2 + (p >> 3)) * 8 + (n & 7)) * 4 + (p & 3)) * 2)
           + ((p >> 2) & 1);
}

// ---------------------------------------------------------------------------
// RoPE table init
// ---------------------------------------------------------------------------
__global__ void rope_init()
{
    int idx = blockIdx.x * blockDim.x + threadIdx.x;  // 0..65535
    int t = idx >> 5;
    int i = idx & 31;
    float theta = powf(10000.0f, (float)i * (-2.0f / 64.0f));
    float ang = (float)t * theta;
    float sn, cs;
    sincosf(ang, &sn, &cs);
    g_rope[idx] = make_float2(cs, sn);
}

// ---------------------------------------------------------------------------
// Pack ALL THREE operands in one launch (fused; grid.y: 0-63 x -> g_xt (A),
// 64-87 w_kqv -> g_wk (B), 88-95 w_proj -> g_wp (B)). grid = (32, 96).
// ---------------------------------------------------------------------------
__global__ void __launch_bounds__(256) pack_all(const float* __restrict__ x,
                                                const float* __restrict__ wk,
                                                const float* __restrict__ wp)
{
    __shared__ __align__(16) __half sm[4096];
    const int by = blockIdx.y;
    int sel, mblk;
    const float* src;
    if (by < 64)      { sel = 0; mblk = by;      src = x;  }
    else if (by < 88) { sel = 1; mblk = by - 64; src = wk; }
    else              { sel = 2; mblk = by - 88; src = wp; }
    __half* dst = (sel == 0) ? g_xt : (sel == 1) ? g_wk : g_wp;
    const bool isA = (sel == 0);

    const int k0 = blockIdx.x * 32;
    const int m0 = mblk * 128;
    const int tid = threadIdx.x;

    #pragma unroll
    for (int l = 0; l < 4; l++) {
        int idx = tid + l * 256;          // 1024 float4 slots (128 rows x 8)
        int row = idx >> 3;
        int c4 = (idx & 7) * 4;
        float4 v = *(const float4*)(src + (size_t)(m0 + row) * 1024 + k0 + c4);
        int p = c4 >> 1;                  // even pair index
        __half2 w0 = __floats2half2_rn(v.x, v.y);
        __half2 w1 = __floats2half2_rn(v.z, v.w);
        int o0 = isA ? offA_h(row, p)     : offB_h(row, p);
        int o1 = isA ? offA_h(row, p + 1) : offB_h(row, p + 1);
        *(__half2*)&sm[o0 * 2] = w0;
        *(__half2*)&sm[o1 * 2] = w1;
    }
    __syncthreads();
    size_t gb = ((size_t)mblk * 32 + blockIdx.x) * 4096;  // halves
    #pragma unroll
    for (int l = 0; l < 2; l++) {
        int i = tid + l * 256;            // 512 uint4
        *(uint4*)&dst[gb + (size_t)i * 8] = *(uint4*)&sm[i * 8];
    }
}

// ---------------------------------------------------------------------------
// fp16 tensor-core GEMM on PACKED operands: C[M,N] = A @ W^T, K=1024.
// Block 128x128, BK=32, 256 threads = 8 warps (2x4), warp tile 64x32.
// 3-stage cp.async pipeline, one barrier per 32-k tile.
// MODE 0: A=g_xt, W=g_wk, QKV epilogue (RoPE, fp16 q/k, transposed fp16 v)
// MODE 1: A=g_ao (packed by attention), W=g_wp, proj epilogue (bias -> out)
// ---------------------------------------------------------------------------
template<int MODE>
__global__ void __launch_bounds__(256) gemm_f16(const float* __restrict__ bias,
                                                float* __restrict__ out)
{
    extern __shared__ __align__(16) uint32_t gsm[];
    uint32_t* As = gsm;            // [3][2048 words]
    uint32_t* Ws = gsm + 3 * 2048;

    const int m0 = blockIdx.y * 128;
    const int n0 = blockIdx.x * 128;
    const int tid = threadIdx.x;
    const int wid = tid >> 5;
    const int lane = tid & 31;
    const int wm = wid >> 2;
    const int wn = wid & 3;
    const int gq = lane >> 2;
    const int tq = lane & 3;

    const __half* Abase = (MODE == 1) ? g_ao : g_xt;
    const __half* Wbase = (MODE == 1) ? g_wp : g_wk;
    const __half* Atiles = Abase + (size_t)blockIdx.y * 32 * 4096;
    const __half* Wtiles = Wbase + (size_t)blockIdx.x * 32 * 4096;

    const uint32_t sA = (uint32_t)__cvta_generic_to_shared(As);
    const uint32_t sW = (uint32_t)__cvta_generic_to_shared(Ws);

    float acc[4][4][4];
    #pragma unroll
    for (int mt = 0; mt < 4; mt++)
        #pragma unroll
        for (int nt = 0; nt < 4; nt++)
            #pragma unroll
            for (int r = 0; r < 4; r++) acc[mt][nt][r] = 0.f;

    // prologue: tiles 0,1 (2048 words each operand; 8 words/thread = 2 cpa16)
    #pragma unroll
    for (int p = 0; p < 2; p++) {
        cpa16(sA + (p * 2048 + tid * 8 + 0) * 4, Atiles + (size_t)p * 4096 + tid * 16 + 0);
        cpa16(sA + (p * 2048 + tid * 8 + 4) * 4, Atiles + (size_t)p * 4096 + tid * 16 + 8);
        cpa16(sW + (p * 2048 + tid * 8 + 0) * 4, Wtiles + (size_t)p * 4096 + tid * 16 + 0);
        cpa16(sW + (p * 2048 + tid * 8 + 4) * 4, Wtiles + (size_t)p * 4096 + tid * 16 + 8);
        CP_COMMIT();
    }

    int st = 0;
    for (int kt = 0; kt < 32; kt++) {
        if (kt < 31) { CP_WAIT(1); } else { CP_WAIT(0); }
        __syncthreads();

        if (kt + 2 < 32) {
            int stn = st + 2; if (stn >= 3) stn -= 3;
            const __half* At = Atiles + (size_t)(kt + 2) * 4096;
            const __half* Wt = Wtiles + (size_t)(kt + 2) * 4096;
            cpa16(sA + (stn * 2048 + tid * 8 + 0) * 4, At + tid * 16 + 0);
            cpa16(sA + (stn * 2048 + tid * 8 + 4) * 4, At + tid * 16 + 8);
            cpa16(sW + (stn * 2048 + tid * 8 + 0) * 4, Wt + tid * 16 + 0);
            cpa16(sW + (stn * 2048 + tid * 8 + 4) * 4, Wt + tid * 16 + 8);
            CP_COMMIT();
        }

        const uint32_t* Acur = As + st * 2048;
        const uint32_t* Wcur = Ws + st * 2048;
        #pragma unroll
        for (int ks = 0; ks < 2; ks++) {
            uint4 af[4];
            uint2 bf[4];
            #pragma unroll
            for (int mt = 0; mt < 4; mt++)
                af[mt] = *(const uint4*)&Acur[((((wm * 4 + mt) * 2 + ks) * 8 + gq) * 4 + tq) * 4];
            #pragma unroll
            for (int nt = 0; nt < 4; nt++)
                bf[nt] = *(const uint2*)&Wcur[((((wn * 4 + nt) * 2 + ks) * 8 + gq) * 4 + tq) * 2];
            #pragma unroll
            for (int mt = 0; mt < 4; mt++)
                #pragma unroll
                for (int nt = 0; nt < 4; nt++)
                    mma_f16(acc[mt][nt], af[mt].x, af[mt].y, af[mt].z, af[mt].w,
                            bf[nt].x, bf[nt].y);
        }
        st = (st == 2) ? 0 : st + 1;
    }

    if (MODE == 0) {
        const float QSC = 0.125f * 1.4426950408889634f;  // scale * log2(e)
        #pragma unroll
        for (int mt = 0; mt < 4; mt++) {
            #pragma unroll
            for (int r = 0; r < 2; r++) {
                int m = m0 + wm * 64 + mt * 16 + gq + r * 8;
                int bb = m >> 11;
                int tt = m & 2047;
                #pragma unroll
                for (int nt = 0; nt < 4; nt++) {
                    int col = n0 + wn * 32 + nt * 8 + 2 * tq;
                    int which = col >> 10;
                    int rem = col & 1023;
                    int h = rem >> 6;
                    int d = rem & 63;
                    int bh = bb * Hn + h;
                    float e = acc[mt][nt][r * 2 + 0];
                    float o = acc[mt][nt][r * 2 + 1];
                    if (which == 2) {
                        // V transposed: [bh][d][t]
                        size_t vo = ((size_t)bh * HS + d) * Tn + tt;
                        g_vt[vo]      = __float2half_rn(e);
                        g_vt[vo + Tn] = __float2half_rn(o);
                    } else {
                        float2 cs = g_rope[tt * 32 + (d >> 1)];
                        float t1 = e * cs.x - o * cs.y;
                        float t2 = e * cs.y + o * cs.x;
                        size_t off = ((size_t)bh * Tn + tt) * HS + d;
                        if (which == 0) {
                            *(__half2*)(g_k + off) = __floats2half2_rn(t1, t2);
                        } else {
                            *(__half2*)(g_q + off) = __floats2half2_rn(t1 * QSC, t2 * QSC);
                        }
                    }
                }
            }
        }
    } else {
        #pragma unroll
        for (int mt = 0; mt < 4; mt++) {
            #pragma unroll
            for (int r = 0; r < 2; r++) {
                int m = m0 + wm * 64 + mt * 16 + gq + r * 8;
                #pragma unroll
                for (int nt = 0; nt < 4; nt++) {
                    int col = n0 + wn * 32 + nt * 8 + 2 * tq;
                    float2 v2;
                    v2.x = acc[mt][nt][r * 2 + 0] + bias[col + 0];
                    v2.y = acc[mt][nt][r * 2 + 1] + bias[col + 1];
                    *(float2*)(out + (size_t)m * 1024 + col) = v2;
                }
            }
        }
    }
}

// ---------------------------------------------------------------------------
// fp16 tensor-core causal flash attention (mma m16n8k16), m32 warp tiles.
// Block: 128 q-rows, 4 warps x m32, 3 CTAs/SM (12 warps/SM; reg cap 170).
// 2-stage cp.async K/Vt pipeline. V pre-transposed (g_vt).
// Epilogue packs fp16 A-tiles into g_ao for the proj GEMM.
// grid = (16, 64); heavy q-blocks first. smem pitch 36 words (72 halves).
// ---------------------------------------------------------------------------
#define AT_PITCH 36                       // words per 64-half row
#define KS_ST (64*AT_PITCH)               // 2304 words per stage
#define SMEM_ATTN ((2*KS_ST*2 + 128*AT_PITCH) * 4)   // K,Vt double-buffer + Ps

__global__ void __launch_bounds__(128, 3) attn_mma()
{
    extern __shared__ __align__(16) uint32_t smw[];
    uint32_t* KsB = smw;                  // [2][64][36]
    uint32_t* VsB = KsB + 2 * KS_ST;      // [2][64][36]
    uint32_t* Ps  = VsB + 2 * KS_ST;      // [128][36]  Q staging / P / O packing

    const int bh = blockIdx.y;
    const int qt = gridDim.x - 1 - blockIdx.x;   // heavy blocks first
    const int tid = threadIdx.x;
    const int wid = tid >> 5;      // 0..3
    const int lane = tid & 31;
    const int gq = lane >> 2;
    const int tq = lane & 3;
    const int qb = qt * 128;
    const int wrow = wid * 32;

    const __half* Qp = g_q + (size_t)bh * Tn * HS;
    const __half* Kp = g_k + (size_t)bh * Tn * HS;
    const __half* Vtp = g_vt + (size_t)bh * HS * Tn;

    const uint32_t sK = (uint32_t)__cvta_generic_to_shared(KsB);
    const uint32_t sV = (uint32_t)__cvta_generic_to_shared(VsB);

    // K/Vt staging: 64 rows x 8 chunks(16B); 512 chunks / 128 thr = 4 each
    #pragma unroll
    for (int l = 0; l < 4; l++) {
        int c = tid + l * 128;
        int rr = c >> 3;
        int ci = c & 7;
        cpa16(sK + (rr * AT_PITCH + ci * 4) * 4, Kp + (size_t)rr * HS + ci * 8);
        cpa16(sV + (rr * AT_PITCH + ci * 4) * 4, Vtp + (size_t)rr * Tn + ci * 8);
    }
    CP_COMMIT();

    // stage Q (128 rows x 8 chunks = 1024 chunks / 128 thr = 8 each)
    #pragma unroll
    for (int l = 0; l < 8; l++) {
        int c = tid + l * 128;
        int rr = c >> 3;
        int ci = c & 7;
        uint4 v = *(const uint4*)(Qp + (size_t)(qb + rr) * HS + ci * 8);
        *(uint4*)&Ps[rr * AT_PITCH + ci * 4] = v;
    }
    __syncthreads();

    int roff[2][2];
    #pragma unroll
    for (int s = 0; s < 2; s++) {
        roff[s][0] = (wrow + 16 * s + gq) * AT_PITCH;
        roff[s][1] = (wrow + 16 * s + gq + 8) * AT_PITCH;
    }

    // Q fragments: [s][kk(4 k16-steps)][4 regs]
    uint32_t qf[2][4][4];
    #pragma unroll
    for (int s = 0; s < 2; s++)
        #pragma unroll
        for (int kk = 0; kk < 4; kk++) {
            qf[s][kk][0] = Ps[roff[s][0] + kk * 8 + tq];
            qf[s][kk][1] = Ps[roff[s][1] + kk * 8 + tq];
            qf[s][kk][2] = Ps[roff[s][0] + kk * 8 + tq + 4];
            qf[s][kk][3] = Ps[roff[s][1] + kk * 8 + tq + 4];
        }

    float O[2][8][4];
    #pragma unroll
    for (int s = 0; s < 2; s++)
        #pragma unroll
        for (int nt = 0; nt < 8; nt++)
            #pragma unroll
            for (int r = 0; r < 4; r++) O[s][nt][r] = 0.f;
    float mrow[2][2], lrow_[2][2];
    #pragma unroll
    for (int s = 0; s < 2; s++) {
        mrow[s][0] = -INFINITY; mrow[s][1] = -INFINITY;
        lrow_[s][0] = 0.f;      lrow_[s][1] = 0.f;
    }

    const int ntiles = 2 * qt + 2;
    int st = 0;
    for (int kt = 0; kt < ntiles; kt++) {
        const int k0 = kt * 64;
        CP_WAIT(0);
        __syncthreads();

        if (kt + 1 < ntiles) {
            int stn = st ^ 1;
            #pragma unroll
            for (int l = 0; l < 4; l++) {
                int c = tid + l * 128;
                int rr = c >> 3;
                int ci = c & 7;
                cpa16(sK + (stn * KS_ST + rr * AT_PITCH + ci * 4) * 4,
                      Kp + (size_t)(k0 + 64 + rr) * HS + ci * 8);
                cpa16(sV + (stn * KS_ST + rr * AT_PITCH + ci * 4) * 4,
                      Vtp + (size_t)rr * Tn + k0 + 64 + ci * 8);
            }
            CP_COMMIT();
        }

        if (k0 <= qb + wrow + 31) {
            const uint32_t* Ks = KsB + st * KS_ST;
            const uint32_t* Vs = VsB + st * KS_ST;

            // ---- S = Q K^T ----
            float S[2][8][4];
            #pragma unroll
            for (int s = 0; s < 2; s++)
                #pragma unroll
                for (int nt = 0; nt < 8; nt++)
                    #pragma unroll
                    for (int r = 0; r < 4; r++) S[s][nt][r] = 0.f;

            #pragma unroll
            for (int kk = 0; kk < 4; kk++) {
                #pragma unroll
                for (int nt = 0; nt < 8; nt++) {
                    uint32_t b0 = Ks[(nt * 8 + gq) * AT_PITCH + kk * 8 + tq];
                    uint32_t b1 = Ks[(nt * 8 + gq) * AT_PITCH + kk * 8 + tq + 4];
                    mma_f16(S[0][nt], qf[0][kk][0], qf[0][kk][1], qf[0][kk][2], qf[0][kk][3], b0, b1);
                    mma_f16(S[1][nt], qf[1][kk][0], qf[1][kk][1], qf[1][kk][2], qf[1][kk][3], b0, b1);
                }
            }

            // ---- causal mask ----
            if (k0 + 63 > qb + wrow) {
                #pragma unroll
                for (int s = 0; s < 2; s++) {
                    int row0 = qb + wrow + 16 * s + gq;
                    #pragma unroll
                    for (int nt = 0; nt < 8; nt++) {
                        int col = k0 + nt * 8 + 2 * tq;
                        if (col     > row0)     S[s][nt][0] = -INFINITY;
                        if (col + 1 > row0)     S[s][nt][1] = -INFINITY;
                        if (col     > row0 + 8) S[s][nt][2] = -INFINITY;
                        if (col + 1 > row0 + 8) S[s][nt][3] = -INFINITY;
                    }
                }
            }

            // ---- online softmax + fp16 P store ----
            __syncwarp();
            #pragma unroll
            for (int s = 0; s < 2; s++) {
                float cm0 = -INFINITY, cm1 = -INFINITY;
                #pragma unroll
                for (int nt = 0; nt < 8; nt++) {
                    cm0 = fmaxf(cm0, fmaxf(S[s][nt][0], S[s][nt][1]));
                    cm1 = fmaxf(cm1, fmaxf(S[s][nt][2], S[s][nt][3]));
                }
                cm0 = fmaxf(cm0, __shfl_xor_sync(0xffffffff, cm0, 1));
                cm0 = fmaxf(cm0, __shfl_xor_sync(0xffffffff, cm0, 2));
                cm1 = fmaxf(cm1, __shfl_xor_sync(0xffffffff, cm1, 1));
                cm1 = fmaxf(cm1, __shfl_xor_sync(0xffffffff, cm1, 2));

                float mn0 = fmaxf(mrow[s][0], cm0);
                float mn1 = fmaxf(mrow[s][1], cm1);
                float c0 = ex2(mrow[s][0] - mn0);
                float c1 = ex2(mrow[s][1] - mn1);
                lrow_[s][0] *= c0; lrow_[s][1] *= c1;
                #pragma unroll
                for (int nt = 0; nt < 8; nt++) {
                    O[s][nt][0] *= c0; O[s][nt][1] *= c0;
                    O[s][nt][2] *= c1; O[s][nt][3] *= c1;
                }
                mrow[s][0] = mn0; mrow[s][1] = mn1;

                #pragma unroll
                for (int nt = 0; nt < 8; nt++) {
                    float p0 = ex2(S[s][nt][0] - mn0);
                    float p1 = ex2(S[s][nt][1] - mn0);
                    float p2 = ex2(S[s][nt][2] - mn1);
                    float p3 = ex2(S[s][nt][3] - mn1);
                    lrow_[s][0] += p0 + p1;
                    lrow_[s][1] += p2 + p3;
                    // key pair index = nt*4 + tq
                    __half2 w0 = __floats2half2_rn(p0, p1);
                    __half2 w1 = __floats2half2_rn(p2, p3);
                    Ps[roff[s][0] + nt * 4 + tq] = *(uint32_t*)&w0;
                    Ps[roff[s][1] + nt * 4 + tq] = *(uint32_t*)&w1;
                }
            }
            __syncwarp();

            // ---- O += P V ----
            #pragma unroll
            for (int kk = 0; kk < 4; kk++) {
                uint32_t a[2][4];
                #pragma unroll
                for (int s = 0; s < 2; s++) {
                    a[s][0] = Ps[roff[s][0] + kk * 8 + tq];
                    a[s][1] = Ps[roff[s][1] + kk * 8 + tq];
                    a[s][2] = Ps[roff[s][0] + kk * 8 + tq + 4];
                    a[s][3] = Ps[roff[s][1] + kk * 8 + tq + 4];
                }
                #pragma unroll
                for (int nt = 0; nt < 8; nt++) {
                    uint32_t b0 = Vs[(nt * 8 + gq) * AT_PITCH + kk * 8 + tq];
                    uint32_t b1 = Vs[(nt * 8 + gq) * AT_PITCH + kk * 8 + tq + 4];
                    mma_f16(O[0][nt], a[0][0], a[0][1], a[0][2], a[0][3], b0, b1);
                    mma_f16(O[1][nt], a[1][0], a[1][1], a[1][2], a[1][3], b0, b1);
                }
            }
        }
        st ^= 1;
    }

    // ---- finalize: pack normalized O into fp16 A-tiles in g_ao ----
    const int bb = bh >> 4;
    const int h = bh & 15;
    __syncthreads();   // all warps done with Ps / mainloop
    #pragma unroll
    for (int s = 0; s < 2; s++) {
        float l0 = lrow_[s][0], l1 = lrow_[s][1];
        l0 += __shfl_xor_sync(0xffffffff, l0, 1);
        l0 += __shfl_xor_sync(0xffffffff, l0, 2);
        l1 += __shfl_xor_sync(0xffffffff, l1, 1);
        l1 += __shfl_xor_sync(0xffffffff, l1, 2);
        float inv0 = 1.f / l0;
        float inv1 = 1.f / l1;
        int m0l = wrow + 16 * s + gq;
        int m1l = m0l + 8;
        #pragma unroll
        for (int nt = 0; nt < 8; nt++) {
            int pg = nt * 4 + tq;          // col pair 0..31 within head
            int ktl = pg >> 4;             // local k-tile (d 0..31 / 32..63)
            int pin = pg & 15;
            __half2 w0 = __floats2half2_rn(O[s][nt][0] * inv0, O[s][nt][1] * inv0);
            __half2 w1 = __floats2half2_rn(O[s][nt][2] * inv1, O[s][nt][3] * inv1);
            Ps[ktl * 2048 + offA_h(m0l, pin)] = *(uint32_t*)&w0;
            Ps[ktl * 2048 + offA_h(m1l, pin)] = *(uint32_t*)&w1;
        }
    }
    __syncthreads();
    // store 2 tiles = 4096 words = 8192 halves = 1024 uint4; 8 per thread
    {
        __half* dst = g_ao + (((size_t)(bb * 16 + qt) * 32) + h * 2) * 4096;
        #pragma unroll
        for (int l = 0; l < 8; l++) {
            int i = tid + l * 128;        // 0..1023
            *(uint4*)&dst[(size_t)i * 8] = *(uint4*)&Ps[i * 4];
        }
    }
}

// ---------------------------------------------------------------------------
extern "C" void kernel_launch(void* const* d_in, const int* in_sizes, int n_in,
                              void* d_out, int out_size)
{
    const float* x      = (const float*)d_in[0];
    const float* w_kqv  = (const float*)d_in[1];
    const float* w_proj = (const float*)d_in[2];
    const float* b_proj = (const float*)d_in[3];
    float* out = (float*)d_out;

    cudaFuncSetAttribute(attn_mma, cudaFuncAttributeMaxDynamicSharedMemorySize, SMEM_ATTN);
    cudaFuncSetAttribute(gemm_f16<0>, cudaFuncAttributeMaxDynamicSharedMemorySize, 49152);
    cudaFuncSetAttribute(gemm_f16<1>, cudaFuncAttributeMaxDynamicSharedMemorySize, 49152);

    rope_init<<<64, 1024>>>();
    {
        dim3 gp(32, 96);             // fused: x (64) + w_kqv (24) + w_proj (8)
        pack_all<<<gp, 256>>>(x, w_kqv, w_proj);
    }

    dim3 g1(3*Dn/128, Mrows/128);   // 24 x 64
    gemm_f16<0><<<g1, 256, 49152>>>(nullptr, nullptr);

    dim3 g2(Tn/128, Bn*Hn);         // 16 x 64
    attn_mma<<<g2, 128, SMEM_ATTN>>>();

    dim3 g3(Dn/128, Mrows/128);     // 8 x 64
    gemm_f16<1><<<g3, 256, 49152>>>(b_proj, out);
}

// round 13
// speedup vs baseline: 1.1401x; 1.1401x over previous
#include <cuda_runtime.h>
#include <cuda_fp16.h>
#include <math.h>
#include <stdint.h>

// Problem constants
#define Bn 4
#define Tn 2048
#define Dn 1024
#define Hn 16
#define HS 64
#define Mrows (Bn*Tn)          // 8192

// Scratch (device globals; no runtime allocation allowed)
__device__ __half g_q [(size_t)Bn*Hn*Tn*HS];   // [B,H,T,64] rope'd+scaled fp16
__device__ __half g_k [(size_t)Bn*Hn*Tn*HS];   // [B,H,T,64] rope'd fp16
__device__ __half g_vt[(size_t)Bn*Hn*HS*Tn];   // [B,H,64,T] V TRANSPOSED fp16
__device__ __half g_ao[(size_t)Mrows*Dn];      // attn out, packed fp16 A-tiles
__device__ float2 g_rope[Tn*32];               // (cos, sin) table
// fragment-major packed fp16 operands: [rowblk][ktile(32-k)][4096 halves]
__device__ __half g_xt[(size_t)Mrows*Dn];
__device__ __half g_wk[(size_t)3*Dn*Dn];
__device__ __half g_wp[(size_t)Dn*Dn];

// ---------------------------------------------------------------------------
// helpers
// ---------------------------------------------------------------------------
__device__ __forceinline__ float ex2(float x) {
    float y;
    asm("ex2.approx.f32 %0, %1;" : "=f"(y) : "f"(x));
    return y;
}

// fp16 mma: D(f32) += A(f16 m16k16) * B(f16 k16n8)
__device__ __forceinline__ void mma_f16(float c[4],
                                        uint32_t a0, uint32_t a1, uint32_t a2, uint32_t a3,
                                        uint32_t b0, uint32_t b1)
{
    asm volatile(
        "mma.sync.aligned.m16n8k16.row.col.f32.f16.f16.f32 "
        "{%0,%1,%2,%3}, {%4,%5,%6,%7}, {%8,%9}, {%0,%1,%2,%3};\n"
        : "+f"(c[0]), "+f"(c[1]), "+f"(c[2]), "+f"(c[3])
        : "r"(a0), "r"(a1), "r"(a2), "r"(a3), "r"(b0), "r"(b1));
}

__device__ __forceinline__ void cpa16(uint32_t dst_smem, const void* src) {
    asm volatile("cp.async.cg.shared.global [%0], [%1], 16;" :: "r"(dst_smem), "l"(src));
}
#define CP_COMMIT()  asm volatile("cp.async.commit_group;")
#define CP_WAIT(n)   asm volatile("cp.async.wait_group " #n ";")

__device__ __forceinline__ uint32_t packh2(float a, float b) {
    __half2 h = __floats2half2_rn(a, b);
    return *(uint32_t*)&h;
}

// word (32-bit = 2 halves) offset within a 128x32 fp16 tile (2048 words)
// p = k-pair index 0..15 (k = 2p)
__device__ __forceinline__ int offA_h(int m, int p) {
    return (((((m >> 4) * 2 + (p >> 3)) * 8 + (m & 7)) * 4 + (p & 3)) * 4)
           + ((p >> 2) & 1) * 2 + ((m >> 3) & 1);
}
__device__ __forceinline__ int offB_h(int n, int p) {
    return (((((n >> 3) * 2 + (p >> 3)) * 8 + (n & 7)) * 4 + (p & 3)) * 2)
           + ((p >> 2) & 1);
}

// ---------------------------------------------------------------------------
// RoPE table init
// ---------------------------------------------------------------------------
__global__ void rope_init()
{
    int idx = blockIdx.x * blockDim.x + threadIdx.x;  // 0..65535
    int t = idx >> 5;
    int i = idx & 31;
    float theta = powf(10000.0f, (float)i * (-2.0f / 64.0f));
    float ang = (float)t * theta;
    float sn, cs;
    sincosf(ang, &sn, &cs);
    g_rope[idx] = make_float2(cs, sn);
}

// ---------------------------------------------------------------------------
// Pack ALL THREE operands in one launch (fused; grid.y: 0-63 x -> g_xt (A),
// 64-87 w_kqv -> g_wk (B), 88-95 w_proj -> g_wp (B)). grid = (32, 96).
// ---------------------------------------------------------------------------
__global__ void __launch_bounds__(256) pack_all(const float* __restrict__ x,
                                                const float* __restrict__ wk,
                                                const float* __restrict__ wp)
{
    __shared__ __align__(16) __half sm[4096];
    const int by = blockIdx.y;
    int sel, mblk;
    const float* src;
    if (by < 64)      { sel = 0; mblk = by;      src = x;  }
    else if (by < 88) { sel = 1; mblk = by - 64; src = wk; }
    else              { sel = 2; mblk = by - 88; src = wp; }
    __half* dst = (sel == 0) ? g_xt : (sel == 1) ? g_wk : g_wp;
    const bool isA = (sel == 0);

    const int k0 = blockIdx.x * 32;
    const int m0 = mblk * 128;
    const int tid = threadIdx.x;

    #pragma unroll
    for (int l = 0; l < 4; l++) {
        int idx = tid + l * 256;
        int row = idx >> 3;
        int c4 = (idx & 7) * 4;
        float4 v = *(const float4*)(src + (size_t)(m0 + row) * 1024 + k0 + c4);
        int p = c4 >> 1;
        __half2 w0 = __floats2half2_rn(v.x, v.y);
        __half2 w1 = __floats2half2_rn(v.z, v.w);
        int o0 = isA ? offA_h(row, p)     : offB_h(row, p);
        int o1 = isA ? offA_h(row, p + 1) : offB_h(row, p + 1);
        *(__half2*)&sm[o0 * 2] = w0;
        *(__half2*)&sm[o1 * 2] = w1;
    }
    __syncthreads();
    size_t gb = ((size_t)mblk * 32 + blockIdx.x) * 4096;
    #pragma unroll
    for (int l = 0; l < 2; l++) {
        int i = tid + l * 256;
        *(uint4*)&dst[gb + (size_t)i * 8] = *(uint4*)&sm[i * 8];
    }
}

// ---------------------------------------------------------------------------
// fp16 tensor-core GEMM on PACKED operands: C[M,N] = A @ W^T, K=1024.
// Block 128x128, BK=32, 256 threads = 8 warps (2x4), warp tile 64x32.
// 3-stage cp.async pipeline, one barrier per 32-k tile.
// MODE 0: A=g_xt, W=g_wk, QKV epilogue (RoPE, fp16 q/k, transposed fp16 v)
// MODE 1: A=g_ao (packed by attention), W=g_wp, proj epilogue (bias -> out)
// ---------------------------------------------------------------------------
template<int MODE>
__global__ void __launch_bounds__(256) gemm_f16(const float* __restrict__ bias,
                                                float* __restrict__ out)
{
    extern __shared__ __align__(16) uint32_t gsm[];
    uint32_t* As = gsm;            // [3][2048 words]
    uint32_t* Ws = gsm + 3 * 2048;

    const int m0 = blockIdx.y * 128;
    const int n0 = blockIdx.x * 128;
    const int tid = threadIdx.x;
    const int wid = tid >> 5;
    const int lane = tid & 31;
    const int wm = wid >> 2;
    const int wn = wid & 3;
    const int gq = lane >> 2;
    const int tq = lane & 3;

    const __half* Abase = (MODE == 1) ? g_ao : g_xt;
    const __half* Wbase = (MODE == 1) ? g_wp : g_wk;
    const __half* Atiles = Abase + (size_t)blockIdx.y * 32 * 4096;
    const __half* Wtiles = Wbase + (size_t)blockIdx.x * 32 * 4096;

    const uint32_t sA = (uint32_t)__cvta_generic_to_shared(As);
    const uint32_t sW = (uint32_t)__cvta_generic_to_shared(Ws);

    float acc[4][4][4];
    #pragma unroll
    for (int mt = 0; mt < 4; mt++)
        #pragma unroll
        for (int nt = 0; nt < 4; nt++)
            #pragma unroll
            for (int r = 0; r < 4; r++) acc[mt][nt][r] = 0.f;

    #pragma unroll
    for (int p = 0; p < 2; p++) {
        cpa16(sA + (p * 2048 + tid * 8 + 0) * 4, Atiles + (size_t)p * 4096 + tid * 16 + 0);
        cpa16(sA + (p * 2048 + tid * 8 + 4) * 4, Atiles + (size_t)p * 4096 + tid * 16 + 8);
        cpa16(sW + (p * 2048 + tid * 8 + 0) * 4, Wtiles + (size_t)p * 4096 + tid * 16 + 0);
        cpa16(sW + (p * 2048 + tid * 8 + 4) * 4, Wtiles + (size_t)p * 4096 + tid * 16 + 8);
        CP_COMMIT();
    }

    int st = 0;
    for (int kt = 0; kt < 32; kt++) {
        if (kt < 31) { CP_WAIT(1); } else { CP_WAIT(0); }
        __syncthreads();

        if (kt + 2 < 32) {
            int stn = st + 2; if (stn >= 3) stn -= 3;
            const __half* At = Atiles + (size_t)(kt + 2) * 4096;
            const __half* Wt = Wtiles + (size_t)(kt + 2) * 4096;
            cpa16(sA + (stn * 2048 + tid * 8 + 0) * 4, At + tid * 16 + 0);
            cpa16(sA + (stn * 2048 + tid * 8 + 4) * 4, At + tid * 16 + 8);
            cpa16(sW + (stn * 2048 + tid * 8 + 0) * 4, Wt + tid * 16 + 0);
            cpa16(sW + (stn * 2048 + tid * 8 + 4) * 4, Wt + tid * 16 + 8);
            CP_COMMIT();
        }

        const uint32_t* Acur = As + st * 2048;
        const uint32_t* Wcur = Ws + st * 2048;
        #pragma unroll
        for (int ks = 0; ks < 2; ks++) {
            uint4 af[4];
            uint2 bf[4];
            #pragma unroll
            for (int mt = 0; mt < 4; mt++)
                af[mt] = *(const uint4*)&Acur[((((wm * 4 + mt) * 2 + ks) * 8 + gq) * 4 + tq) * 4];
            #pragma unroll
            for (int nt = 0; nt < 4; nt++)
                bf[nt] = *(const uint2*)&Wcur[((((wn * 4 + nt) * 2 + ks) * 8 + gq) * 4 + tq) * 2];
            #pragma unroll
            for (int mt = 0; mt < 4; mt++)
                #pragma unroll
                for (int nt = 0; nt < 4; nt++)
                    mma_f16(acc[mt][nt], af[mt].x, af[mt].y, af[mt].z, af[mt].w,
                            bf[nt].x, bf[nt].y);
        }
        st = (st == 2) ? 0 : st + 1;
    }

    if (MODE == 0) {
        const float QSC = 0.125f * 1.4426950408889634f;  // scale * log2(e)
        #pragma unroll
        for (int mt = 0; mt < 4; mt++) {
            #pragma unroll
            for (int r = 0; r < 2; r++) {
                int m = m0 + wm * 64 + mt * 16 + gq + r * 8;
                int bb = m >> 11;
                int tt = m & 2047;
                #pragma unroll
                for (int nt = 0; nt < 4; nt++) {
                    int col = n0 + wn * 32 + nt * 8 + 2 * tq;
                    int which = col >> 10;
                    int rem = col & 1023;
                    int h = rem >> 6;
                    int d = rem & 63;
                    int bh = bb * Hn + h;
                    float e = acc[mt][nt][r * 2 + 0];
                    float o = acc[mt][nt][r * 2 + 1];
                    if (which == 2) {
                        size_t vo = ((size_t)bh * HS + d) * Tn + tt;
                        g_vt[vo]      = __float2half_rn(e);
                        g_vt[vo + Tn] = __float2half_rn(o);
                    } else {
                        float2 cs = g_rope[tt * 32 + (d >> 1)];
                        float t1 = e * cs.x - o * cs.y;
                        float t2 = e * cs.y + o * cs.x;
                        size_t off = ((size_t)bh * Tn + tt) * HS + d;
                        if (which == 0) {
                            *(__half2*)(g_k + off) = __floats2half2_rn(t1, t2);
                        } else {
                            *(__half2*)(g_q + off) = __floats2half2_rn(t1 * QSC, t2 * QSC);
                        }
                    }
                }
            }
        }
    } else {
        #pragma unroll
        for (int mt = 0; mt < 4; mt++) {
            #pragma unroll
            for (int r = 0; r < 2; r++) {
                int m = m0 + wm * 64 + mt * 16 + gq + r * 8;
                #pragma unroll
                for (int nt = 0; nt < 4; nt++) {
                    int col = n0 + wn * 32 + nt * 8 + 2 * tq;
                    float2 v2;
                    v2.x = acc[mt][nt][r * 2 + 0] + bias[col + 0];
                    v2.y = acc[mt][nt][r * 2 + 1] + bias[col + 1];
                    *(float2*)(out + (size_t)m * 1024 + col) = v2;
                }
            }
        }
    }
}

// ---------------------------------------------------------------------------
// fp16 tensor-core causal flash attention (mma m16n8k16), m32 warp tiles.
// Block: 128 q-rows, 4 warps x m32, 2 CTAs/SM (natural regs, no tight cap).
// P stays in REGISTERS: the S-accumulator fragment layout IS the PV A-operand
// layout (a0/a1 = S[2kk] pairs, a2/a3 = S[2kk+1] pairs) -> no smem round-trip.
// 2-stage cp.async K/Vt pipeline; V pre-transposed (g_vt).
// Epilogue packs fp16 A-tiles into g_ao for the proj GEMM.
// grid = (16, 64); heavy q-blocks first. smem pitch 36 words (72 halves).
// ---------------------------------------------------------------------------
#define AT_PITCH 36                       // words per 64-half row
#define KS_ST (64*AT_PITCH)               // 2304 words per stage
#define SMEM_ATTN ((2*KS_ST*2 + 128*AT_PITCH) * 4)   // K,Vt double-buffer + Ps

__global__ void __launch_bounds__(128, 2) attn_mma()
{
    extern __shared__ __align__(16) uint32_t smw[];
    uint32_t* KsB = smw;                  // [2][64][36]
    uint32_t* VsB = KsB + 2 * KS_ST;      // [2][64][36]
    uint32_t* Ps  = VsB + 2 * KS_ST;      // [128][36]  Q staging / O packing

    const int bh = blockIdx.y;
    const int qt = gridDim.x - 1 - blockIdx.x;   // heavy blocks first
    const int tid = threadIdx.x;
    const int wid = tid >> 5;      // 0..3
    const int lane = tid & 31;
    const int gq = lane >> 2;
    const int tq = lane & 3;
    const int qb = qt * 128;
    const int wrow = wid * 32;

    const __half* Qp = g_q + (size_t)bh * Tn * HS;
    const __half* Kp = g_k + (size_t)bh * Tn * HS;
    const __half* Vtp = g_vt + (size_t)bh * HS * Tn;

    const uint32_t sK = (uint32_t)__cvta_generic_to_shared(KsB);
    const uint32_t sV = (uint32_t)__cvta_generic_to_shared(VsB);

    // K/Vt staging: 64 rows x 8 chunks(16B); 512 chunks / 128 thr = 4 each
    #pragma unroll
    for (int l = 0; l < 4; l++) {
        int c = tid + l * 128;
        int rr = c >> 3;
        int ci = c & 7;
        cpa16(sK + (rr * AT_PITCH + ci * 4) * 4, Kp + (size_t)rr * HS + ci * 8);
        cpa16(sV + (rr * AT_PITCH + ci * 4) * 4, Vtp + (size_t)rr * Tn + ci * 8);
    }
    CP_COMMIT();

    // stage Q (128 rows x 8 chunks = 1024 chunks / 128 thr = 8 each)
    #pragma unroll
    for (int l = 0; l < 8; l++) {
        int c = tid + l * 128;
        int rr = c >> 3;
        int ci = c & 7;
        uint4 v = *(const uint4*)(Qp + (size_t)(qb + rr) * HS + ci * 8);
        *(uint4*)&Ps[rr * AT_PITCH + ci * 4] = v;
    }
    __syncthreads();

    int roff[2][2];
    #pragma unroll
    for (int s = 0; s < 2; s++) {
        roff[s][0] = (wrow + 16 * s + gq) * AT_PITCH;
        roff[s][1] = (wrow + 16 * s + gq + 8) * AT_PITCH;
    }

    // Q fragments: [s][kk(4 k16-steps)][4 regs]
    uint32_t qf[2][4][4];
    #pragma unroll
    for (int s = 0; s < 2; s++)
        #pragma unroll
        for (int kk = 0; kk < 4; kk++) {
            qf[s][kk][0] = Ps[roff[s][0] + kk * 8 + tq];
            qf[s][kk][1] = Ps[roff[s][1] + kk * 8 + tq];
            qf[s][kk][2] = Ps[roff[s][0] + kk * 8 + tq + 4];
            qf[s][kk][3] = Ps[roff[s][1] + kk * 8 + tq + 4];
        }

    float O[2][8][4];
    #pragma unroll
    for (int s = 0; s < 2; s++)
        #pragma unroll
        for (int nt = 0; nt < 8; nt++)
            #pragma unroll
            for (int r = 0; r < 4; r++) O[s][nt][r] = 0.f;
    float mrow[2][2], lrow_[2][2];
    #pragma unroll
    for (int s = 0; s < 2; s++) {
        mrow[s][0] = -INFINITY; mrow[s][1] = -INFINITY;
        lrow_[s][0] = 0.f;      lrow_[s][1] = 0.f;
    }

    const int ntiles = 2 * qt + 2;
    int st = 0;
    for (int kt = 0; kt < ntiles; kt++) {
        const int k0 = kt * 64;
        CP_WAIT(0);
        __syncthreads();

        if (kt + 1 < ntiles) {
            int stn = st ^ 1;
            #pragma unroll
            for (int l = 0; l < 4; l++) {
                int c = tid + l * 128;
                int rr = c >> 3;
                int ci = c & 7;
                cpa16(sK + (stn * KS_ST + rr * AT_PITCH + ci * 4) * 4,
                      Kp + (size_t)(k0 + 64 + rr) * HS + ci * 8);
                cpa16(sV + (stn * KS_ST + rr * AT_PITCH + ci * 4) * 4,
                      Vtp + (size_t)rr * Tn + k0 + 64 + ci * 8);
            }
            CP_COMMIT();
        }

        if (k0 <= qb + wrow + 31) {
            const uint32_t* Ks = KsB + st * KS_ST;
            const uint32_t* Vs = VsB + st * KS_ST;

            // ---- S = Q K^T ----
            float S[2][8][4];
            #pragma unroll
            for (int s = 0; s < 2; s++)
                #pragma unroll
                for (int nt = 0; nt < 8; nt++)
                    #pragma unroll
                    for (int r = 0; r < 4; r++) S[s][nt][r] = 0.f;

            #pragma unroll
            for (int kk = 0; kk < 4; kk++) {
                #pragma unroll
                for (int nt = 0; nt < 8; nt++) {
                    uint32_t b0 = Ks[(nt * 8 + gq) * AT_PITCH + kk * 8 + tq];
                    uint32_t b1 = Ks[(nt * 8 + gq) * AT_PITCH + kk * 8 + tq + 4];
                    mma_f16(S[0][nt], qf[0][kk][0], qf[0][kk][1], qf[0][kk][2], qf[0][kk][3], b0, b1);
                    mma_f16(S[1][nt], qf[1][kk][0], qf[1][kk][1], qf[1][kk][2], qf[1][kk][3], b0, b1);
                }
            }

            // ---- causal mask ----
            if (k0 + 63 > qb + wrow) {
                #pragma unroll
                for (int s = 0; s < 2; s++) {
                    int row0 = qb + wrow + 16 * s + gq;
                    #pragma unroll
                    for (int nt = 0; nt < 8; nt++) {
                        int col = k0 + nt * 8 + 2 * tq;
                        if (col     > row0)     S[s][nt][0] = -INFINITY;
                        if (col + 1 > row0)     S[s][nt][1] = -INFINITY;
                        if (col     > row0 + 8) S[s][nt][2] = -INFINITY;
                        if (col + 1 > row0 + 8) S[s][nt][3] = -INFINITY;
                    }
                }
            }

            // ---- online softmax; P packed directly into registers ----
            uint32_t Pr[2][8][2];
            #pragma unroll
            for (int s = 0; s < 2; s++) {
                float cm0 = -INFINITY, cm1 = -INFINITY;
                #pragma unroll
                for (int nt = 0; nt < 8; nt++) {
                    cm0 = fmaxf(cm0, fmaxf(S[s][nt][0], S[s][nt][1]));
                    cm1 = fmaxf(cm1, fmaxf(S[s][nt][2], S[s][nt][3]));
                }
                cm0 = fmaxf(cm0, __shfl_xor_sync(0xffffffff, cm0, 1));
                cm0 = fmaxf(cm0, __shfl_xor_sync(0xffffffff, cm0, 2));
                cm1 = fmaxf(cm1, __shfl_xor_sync(0xffffffff, cm1, 1));
                cm1 = fmaxf(cm1, __shfl_xor_sync(0xffffffff, cm1, 2));

                float mn0 = fmaxf(mrow[s][0], cm0);
                float mn1 = fmaxf(mrow[s][1], cm1);
                float c0 = ex2(mrow[s][0] - mn0);
                float c1 = ex2(mrow[s][1] - mn1);
                lrow_[s][0] *= c0; lrow_[s][1] *= c1;
                #pragma unroll
                for (int nt = 0; nt < 8; nt++) {
                    O[s][nt][0] *= c0; O[s][nt][1] *= c0;
                    O[s][nt][2] *= c1; O[s][nt][3] *= c1;
                }
                mrow[s][0] = mn0; mrow[s][1] = mn1;

                #pragma unroll
                for (int nt = 0; nt < 8; nt++) {
                    float p0 = ex2(S[s][nt][0] - mn0);
                    float p1 = ex2(S[s][nt][1] - mn0);
                    float p2 = ex2(S[s][nt][2] - mn1);
                    float p3 = ex2(S[s][nt][3] - mn1);
                    lrow_[s][0] += p0 + p1;
                    lrow_[s][1] += p2 + p3;
                    Pr[s][nt][0] = packh2(p0, p1);   // rows gq,   keys 8nt+2tq,+1
                    Pr[s][nt][1] = packh2(p2, p3);   // rows gq+8, keys 8nt+2tq,+1
                }
            }

            // ---- O += P V ---- (A frags = Pr directly; B = Vt[d][key] pairs)
            #pragma unroll
            for (int kk = 0; kk < 4; kk++) {
                #pragma unroll
                for (int nt = 0; nt < 8; nt++) {
                    uint32_t b0 = Vs[(nt * 8 + gq) * AT_PITCH + kk * 8 + tq];
                    uint32_t b1 = Vs[(nt * 8 + gq) * AT_PITCH + kk * 8 + tq + 4];
                    mma_f16(O[0][nt], Pr[0][2*kk][0], Pr[0][2*kk][1],
                            Pr[0][2*kk+1][0], Pr[0][2*kk+1][1], b0, b1);
                    mma_f16(O[1][nt], Pr[1][2*kk][0], Pr[1][2*kk][1],
                            Pr[1][2*kk+1][0], Pr[1][2*kk+1][1], b0, b1);
                }
            }
        }
        st ^= 1;
    }

    // ---- finalize: pack normalized O into fp16 A-tiles in g_ao ----
    const int bb = bh >> 4;
    const int h = bh & 15;
    __syncthreads();   // all warps done with Ps / mainloop
    #pragma unroll
    for (int s = 0; s < 2; s++) {
        float l0 = lrow_[s][0], l1 = lrow_[s][1];
        l0 += __shfl_xor_sync(0xffffffff, l0, 1);
        l0 += __shfl_xor_sync(0xffffffff, l0, 2);
        l1 += __shfl_xor_sync(0xffffffff, l1, 1);
        l1 += __shfl_xor_sync(0xffffffff, l1, 2);
        float inv0 = 1.f / l0;
        float inv1 = 1.f / l1;
        int m0l = wrow + 16 * s + gq;
        int m1l = m0l + 8;
        #pragma unroll
        for (int nt = 0; nt < 8; nt++) {
            int pg = nt * 4 + tq;          // col pair 0..31 within head
            int ktl = pg >> 4;             // local k-tile (d 0..31 / 32..63)
            int pin = pg & 15;
            Ps[ktl * 2048 + offA_h(m0l, pin)] = packh2(O[s][nt][0] * inv0, O[s][nt][1] * inv0);
            Ps[ktl * 2048 + offA_h(m1l, pin)] = packh2(O[s][nt][2] * inv1, O[s][nt][3] * inv1);
        }
    }
    __syncthreads();
    // store 2 tiles = 4096 words = 8192 halves = 1024 uint4; 8 per thread
    {
        __half* dst = g_ao + (((size_t)(bb * 16 + qt) * 32) + h * 2) * 4096;
        #pragma unroll
        for (int l = 0; l < 8; l++) {
            int i = tid + l * 128;        // 0..1023
            *(uint4*)&dst[(size_t)i * 8] = *(uint4*)&Ps[i * 4];
        }
    }
}

// ---------------------------------------------------------------------------
extern "C" void kernel_launch(void* const* d_in, const int* in_sizes, int n_in,
                              void* d_out, int out_size)
{
    const float* x      = (const float*)d_in[0];
    const float* w_kqv  = (const float*)d_in[1];
    const float* w_proj = (const float*)d_in[2];
    const float* b_proj = (const float*)d_in[3];
    float* out = (float*)d_out;

    cudaFuncSetAttribute(attn_mma, cudaFuncAttributeMaxDynamicSharedMemorySize, SMEM_ATTN);
    cudaFuncSetAttribute(gemm_f16<0>, cudaFuncAttributeMaxDynamicSharedMemorySize, 49152);
    cudaFuncSetAttribute(gemm_f16<1>, cudaFuncAttributeMaxDynamicSharedMemorySize, 49152);

    rope_init<<<64, 1024>>>();
    {
        dim3 gp(32, 96);             // fused: x (64) + w_kqv (24) + w_proj (8)
        pack_all<<<gp, 256>>>(x, w_kqv, w_proj);
    }

    dim3 g1(3*Dn/128, Mrows/128);   // 24 x 64
    gemm_f16<0><<<g1, 256, 49152>>>(nullptr, nullptr);

    dim3 g2(Tn/128, Bn*Hn);         // 16 x 64
    attn_mma<<<g2, 128, SMEM_ATTN>>>();

    dim3 g3(Dn/128, Mrows/128);     // 8 x 64
    gemm_f16<1><<<g3, 256, 49152>>>(b_proj, out);
}

// round 14
// speedup vs baseline: 1.1409x; 1.0007x over previous
#include <cuda_runtime.h>
#include <cuda_fp16.h>
#include <math.h>
#include <stdint.h>

// Problem constants
#define Bn 4
#define Tn 2048
#define Dn 1024
#define Hn 16
#define HS 64
#define Mrows (Bn*Tn)          // 8192

// Scratch (device globals; no runtime allocation allowed)
__device__ __half g_q [(size_t)Bn*Hn*Tn*HS];   // [B,H,T,64] rope'd+scaled fp16
__device__ __half g_k [(size_t)Bn*Hn*Tn*HS];   // [B,H,T,64] rope'd fp16
__device__ __half g_vt[(size_t)Bn*Hn*HS*Tn];   // [B,H,64,T] V TRANSPOSED fp16
__device__ __half g_ao[(size_t)Mrows*Dn];      // attn out, packed fp16 A-tiles
__device__ float2 g_rope[Tn*32];               // (cos, sin) table
// fragment-major packed fp16 operands: [rowblk][ktile(32-k)][4096 halves]
__device__ __half g_xt[(size_t)Mrows*Dn];
__device__ __half g_wk[(size_t)3*Dn*Dn];
__device__ __half g_wp[(size_t)Dn*Dn];

// ---------------------------------------------------------------------------
// helpers
// ---------------------------------------------------------------------------
__device__ __forceinline__ float ex2(float x) {
    float y;
    asm("ex2.approx.f32 %0, %1;" : "=f"(y) : "f"(x));
    return y;
}

// fp16 mma: D(f32) += A(f16 m16k16) * B(f16 k16n8)
__device__ __forceinline__ void mma_f16(float c[4],
                                        uint32_t a0, uint32_t a1, uint32_t a2, uint32_t a3,
                                        uint32_t b0, uint32_t b1)
{
    asm volatile(
        "mma.sync.aligned.m16n8k16.row.col.f32.f16.f16.f32 "
        "{%0,%1,%2,%3}, {%4,%5,%6,%7}, {%8,%9}, {%0,%1,%2,%3};\n"
        : "+f"(c[0]), "+f"(c[1]), "+f"(c[2]), "+f"(c[3])
        : "r"(a0), "r"(a1), "r"(a2), "r"(a3), "r"(b0), "r"(b1));
}

__device__ __forceinline__ void cpa16(uint32_t dst_smem, const void* src) {
    asm volatile("cp.async.cg.shared.global [%0], [%1], 16;" :: "r"(dst_smem), "l"(src));
}
#define CP_COMMIT()  asm volatile("cp.async.commit_group;")
#define CP_WAIT(n)   asm volatile("cp.async.wait_group " #n ";")

__device__ __forceinline__ uint32_t packh2(float a, float b) {
    __half2 h = __floats2half2_rn(a, b);
    return *(uint32_t*)&h;
}

// word (32-bit = 2 halves) offset within a 128x32 fp16 tile (2048 words)
// p = k-pair index 0..15 (k = 2p)
__device__ __forceinline__ int offA_h(int m, int p) {
    return (((((m >> 4) * 2 + (p >> 3)) * 8 + (m & 7)) * 4 + (p & 3)) * 4)
           + ((p >> 2) & 1) * 2 + ((m >> 3) & 1);
}
__device__ __forceinline__ int offB_h(int n, int p) {
    return (((((n >> 3) * 2 + (p >> 3)) * 8 + (n & 7)) * 4 + (p & 3)) * 2)
           + ((p >> 2) & 1);
}

// ---------------------------------------------------------------------------
// RoPE table init
// ---------------------------------------------------------------------------
__global__ void rope_init()
{
    int idx = blockIdx.x * blockDim.x + threadIdx.x;  // 0..65535
    int t = idx >> 5;
    int i = idx & 31;
    float theta = powf(10000.0f, (float)i * (-2.0f / 64.0f));
    float ang = (float)t * theta;
    float sn, cs;
    sincosf(ang, &sn, &cs);
    g_rope[idx] = make_float2(cs, sn);
}

// ---------------------------------------------------------------------------
// Pack ALL THREE operands in one launch (fused; grid.y: 0-63 x -> g_xt (A),
// 64-87 w_kqv -> g_wk (B), 88-95 w_proj -> g_wp (B)). grid = (32, 96).
// ---------------------------------------------------------------------------
__global__ void __launch_bounds__(256) pack_all(const float* __restrict__ x,
                                                const float* __restrict__ wk,
                                                const float* __restrict__ wp)
{
    __shared__ __align__(16) __half sm[4096];
    const int by = blockIdx.y;
    int sel, mblk;
    const float* src;
    if (by < 64)      { sel = 0; mblk = by;      src = x;  }
    else if (by < 88) { sel = 1; mblk = by - 64; src = wk; }
    else              { sel = 2; mblk = by - 88; src = wp; }
    __half* dst = (sel == 0) ? g_xt : (sel == 1) ? g_wk : g_wp;
    const bool isA = (sel == 0);

    const int k0 = blockIdx.x * 32;
    const int m0 = mblk * 128;
    const int tid = threadIdx.x;

    #pragma unroll
    for (int l = 0; l < 4; l++) {
        int idx = tid + l * 256;
        int row = idx >> 3;
        int c4 = (idx & 7) * 4;
        float4 v = *(const float4*)(src + (size_t)(m0 + row) * 1024 + k0 + c4);
        int p = c4 >> 1;
        __half2 w0 = __floats2half2_rn(v.x, v.y);
        __half2 w1 = __floats2half2_rn(v.z, v.w);
        int o0 = isA ? offA_h(row, p)     : offB_h(row, p);
        int o1 = isA ? offA_h(row, p + 1) : offB_h(row, p + 1);
        *(__half2*)&sm[o0 * 2] = w0;
        *(__half2*)&sm[o1 * 2] = w1;
    }
    __syncthreads();
    size_t gb = ((size_t)mblk * 32 + blockIdx.x) * 4096;
    #pragma unroll
    for (int l = 0; l < 2; l++) {
        int i = tid + l * 256;
        *(uint4*)&dst[gb + (size_t)i * 8] = *(uint4*)&sm[i * 8];
    }
}

// ---------------------------------------------------------------------------
// fp16 tensor-core GEMM on PACKED operands: C[M,N] = A @ W^T, K=1024.
// Block 128x128, BK=32, 256 threads = 8 warps (2x4), warp tile 64x32.
// 3-stage cp.async pipeline, one barrier per 32-k tile.
// MODE 0: A=g_xt, W=g_wk, QKV epilogue (RoPE, fp16 q/k, transposed fp16 v)
// MODE 1: A=g_ao (packed by attention), W=g_wp, proj epilogue (bias -> out)
// ---------------------------------------------------------------------------
template<int MODE>
__global__ void __launch_bounds__(256) gemm_f16(const float* __restrict__ bias,
                                                float* __restrict__ out)
{
    extern __shared__ __align__(16) uint32_t gsm[];
    uint32_t* As = gsm;            // [3][2048 words]
    uint32_t* Ws = gsm + 3 * 2048;

    const int m0 = blockIdx.y * 128;
    const int n0 = blockIdx.x * 128;
    const int tid = threadIdx.x;
    const int wid = tid >> 5;
    const int lane = tid & 31;
    const int wm = wid >> 2;
    const int wn = wid & 3;
    const int gq = lane >> 2;
    const int tq = lane & 3;

    const __half* Abase = (MODE == 1) ? g_ao : g_xt;
    const __half* Wbase = (MODE == 1) ? g_wp : g_wk;
    const __half* Atiles = Abase + (size_t)blockIdx.y * 32 * 4096;
    const __half* Wtiles = Wbase + (size_t)blockIdx.x * 32 * 4096;

    const uint32_t sA = (uint32_t)__cvta_generic_to_shared(As);
    const uint32_t sW = (uint32_t)__cvta_generic_to_shared(Ws);

    float acc[4][4][4];
    #pragma unroll
    for (int mt = 0; mt < 4; mt++)
        #pragma unroll
        for (int nt = 0; nt < 4; nt++)
            #pragma unroll
            for (int r = 0; r < 4; r++) acc[mt][nt][r] = 0.f;

    #pragma unroll
    for (int p = 0; p < 2; p++) {
        cpa16(sA + (p * 2048 + tid * 8 + 0) * 4, Atiles + (size_t)p * 4096 + tid * 16 + 0);
        cpa16(sA + (p * 2048 + tid * 8 + 4) * 4, Atiles + (size_t)p * 4096 + tid * 16 + 8);
        cpa16(sW + (p * 2048 + tid * 8 + 0) * 4, Wtiles + (size_t)p * 4096 + tid * 16 + 0);
        cpa16(sW + (p * 2048 + tid * 8 + 4) * 4, Wtiles + (size_t)p * 4096 + tid * 16 + 8);
        CP_COMMIT();
    }

    int st = 0;
    for (int kt = 0; kt < 32; kt++) {
        if (kt < 31) { CP_WAIT(1); } else { CP_WAIT(0); }
        __syncthreads();

        if (kt + 2 < 32) {
            int stn = st + 2; if (stn >= 3) stn -= 3;
            const __half* At = Atiles + (size_t)(kt + 2) * 4096;
            const __half* Wt = Wtiles + (size_t)(kt + 2) * 4096;
            cpa16(sA + (stn * 2048 + tid * 8 + 0) * 4, At + tid * 16 + 0);
            cpa16(sA + (stn * 2048 + tid * 8 + 4) * 4, At + tid * 16 + 8);
            cpa16(sW + (stn * 2048 + tid * 8 + 0) * 4, Wt + tid * 16 + 0);
            cpa16(sW + (stn * 2048 + tid * 8 + 4) * 4, Wt + tid * 16 + 8);
            CP_COMMIT();
        }

        const uint32_t* Acur = As + st * 2048;
        const uint32_t* Wcur = Ws + st * 2048;
        #pragma unroll
        for (int ks = 0; ks < 2; ks++) {
            uint4 af[4];
            uint2 bf[4];
            #pragma unroll
            for (int mt = 0; mt < 4; mt++)
                af[mt] = *(const uint4*)&Acur[((((wm * 4 + mt) * 2 + ks) * 8 + gq) * 4 + tq) * 4];
            #pragma unroll
            for (int nt = 0; nt < 4; nt++)
                bf[nt] = *(const uint2*)&Wcur[((((wn * 4 + nt) * 2 + ks) * 8 + gq) * 4 + tq) * 2];
            #pragma unroll
            for (int mt = 0; mt < 4; mt++)
                #pragma unroll
                for (int nt = 0; nt < 4; nt++)
                    mma_f16(acc[mt][nt], af[mt].x, af[mt].y, af[mt].z, af[mt].w,
                            bf[nt].x, bf[nt].y);
        }
        st = (st == 2) ? 0 : st + 1;
    }

    if (MODE == 0) {
        const float QSC = 0.125f * 1.4426950408889634f;  // scale * log2(e)
        #pragma unroll
        for (int mt = 0; mt < 4; mt++) {
            #pragma unroll
            for (int r = 0; r < 2; r++) {
                int m = m0 + wm * 64 + mt * 16 + gq + r * 8;
                int bb = m >> 11;
                int tt = m & 2047;
                #pragma unroll
                for (int nt = 0; nt < 4; nt++) {
                    int col = n0 + wn * 32 + nt * 8 + 2 * tq;
                    int which = col >> 10;
                    int rem = col & 1023;
                    int h = rem >> 6;
                    int d = rem & 63;
                    int bh = bb * Hn + h;
                    float e = acc[mt][nt][r * 2 + 0];
                    float o = acc[mt][nt][r * 2 + 1];
                    if (which == 2) {
                        size_t vo = ((size_t)bh * HS + d) * Tn + tt;
                        g_vt[vo]      = __float2half_rn(e);
                        g_vt[vo + Tn] = __float2half_rn(o);
                    } else {
                        float2 cs = g_rope[tt * 32 + (d >> 1)];
                        float t1 = e * cs.x - o * cs.y;
                        float t2 = e * cs.y + o * cs.x;
                        size_t off = ((size_t)bh * Tn + tt) * HS + d;
                        if (which == 0) {
                            *(__half2*)(g_k + off) = __floats2half2_rn(t1, t2);
                        } else {
                            *(__half2*)(g_q + off) = __floats2half2_rn(t1 * QSC, t2 * QSC);
                        }
                    }
                }
            }
        }
    } else {
        #pragma unroll
        for (int mt = 0; mt < 4; mt++) {
            #pragma unroll
            for (int r = 0; r < 2; r++) {
                int m = m0 + wm * 64 + mt * 16 + gq + r * 8;
                #pragma unroll
                for (int nt = 0; nt < 4; nt++) {
                    int col = n0 + wn * 32 + nt * 8 + 2 * tq;
                    float2 v2;
                    v2.x = acc[mt][nt][r * 2 + 0] + bias[col + 0];
                    v2.y = acc[mt][nt][r * 2 + 1] + bias[col + 1];
                    *(float2*)(out + (size_t)m * 1024 + col) = v2;
                }
            }
        }
    }
}

// ---------------------------------------------------------------------------
// fp16 tensor-core causal flash attention (mma m16n8k16), m32 warp tiles.
// Block: 128 q-rows, 4 warps x m32, 2 CTAs/SM. P in registers (S fragment
// layout == PV A-operand layout). Online-softmax O-rescale is SKIPPED via a
// warp-uniform vote when no row's running max increased this tile (c == 1).
// 2-stage cp.async K/Vt pipeline; V pre-transposed (g_vt).
// Epilogue packs fp16 A-tiles into g_ao for the proj GEMM.
// grid = (16, 64); heavy q-blocks first. smem pitch 36 words (72 halves).
// ---------------------------------------------------------------------------
#define AT_PITCH 36                       // words per 64-half row
#define KS_ST (64*AT_PITCH)               // 2304 words per stage
#define SMEM_ATTN ((2*KS_ST*2 + 128*AT_PITCH) * 4)   // K,Vt double-buffer + Ps

__global__ void __launch_bounds__(128, 2) attn_mma()
{
    extern __shared__ __align__(16) uint32_t smw[];
    uint32_t* KsB = smw;                  // [2][64][36]
    uint32_t* VsB = KsB + 2 * KS_ST;      // [2][64][36]
    uint32_t* Ps  = VsB + 2 * KS_ST;      // [128][36]  Q staging / O packing

    const int bh = blockIdx.y;
    const int qt = gridDim.x - 1 - blockIdx.x;   // heavy blocks first
    const int tid = threadIdx.x;
    const int wid = tid >> 5;      // 0..3
    const int lane = tid & 31;
    const int gq = lane >> 2;
    const int tq = lane & 3;
    const int qb = qt * 128;
    const int wrow = wid * 32;

    const __half* Qp = g_q + (size_t)bh * Tn * HS;
    const __half* Kp = g_k + (size_t)bh * Tn * HS;
    const __half* Vtp = g_vt + (size_t)bh * HS * Tn;

    const uint32_t sK = (uint32_t)__cvta_generic_to_shared(KsB);
    const uint32_t sV = (uint32_t)__cvta_generic_to_shared(VsB);

    // K/Vt staging: 64 rows x 8 chunks(16B); 512 chunks / 128 thr = 4 each
    #pragma unroll
    for (int l = 0; l < 4; l++) {
        int c = tid + l * 128;
        int rr = c >> 3;
        int ci = c & 7;
        cpa16(sK + (rr * AT_PITCH + ci * 4) * 4, Kp + (size_t)rr * HS + ci * 8);
        cpa16(sV + (rr * AT_PITCH + ci * 4) * 4, Vtp + (size_t)rr * Tn + ci * 8);
    }
    CP_COMMIT();

    // stage Q (128 rows x 8 chunks = 1024 chunks / 128 thr = 8 each)
    #pragma unroll
    for (int l = 0; l < 8; l++) {
        int c = tid + l * 128;
        int rr = c >> 3;
        int ci = c & 7;
        uint4 v = *(const uint4*)(Qp + (size_t)(qb + rr) * HS + ci * 8);
        *(uint4*)&Ps[rr * AT_PITCH + ci * 4] = v;
    }
    __syncthreads();

    int roff[2][2];
    #pragma unroll
    for (int s = 0; s < 2; s++) {
        roff[s][0] = (wrow + 16 * s + gq) * AT_PITCH;
        roff[s][1] = (wrow + 16 * s + gq + 8) * AT_PITCH;
    }

    // Q fragments: [s][kk(4 k16-steps)][4 regs]
    uint32_t qf[2][4][4];
    #pragma unroll
    for (int s = 0; s < 2; s++)
        #pragma unroll
        for (int kk = 0; kk < 4; kk++) {
            qf[s][kk][0] = Ps[roff[s][0] + kk * 8 + tq];
            qf[s][kk][1] = Ps[roff[s][1] + kk * 8 + tq];
            qf[s][kk][2] = Ps[roff[s][0] + kk * 8 + tq + 4];
            qf[s][kk][3] = Ps[roff[s][1] + kk * 8 + tq + 4];
        }

    float O[2][8][4];
    #pragma unroll
    for (int s = 0; s < 2; s++)
        #pragma unroll
        for (int nt = 0; nt < 8; nt++)
            #pragma unroll
            for (int r = 0; r < 4; r++) O[s][nt][r] = 0.f;
    float mrow[2][2], lrow_[2][2];
    #pragma unroll
    for (int s = 0; s < 2; s++) {
        mrow[s][0] = -INFINITY; mrow[s][1] = -INFINITY;
        lrow_[s][0] = 0.f;      lrow_[s][1] = 0.f;
    }

    const int ntiles = 2 * qt + 2;
    int st = 0;
    for (int kt = 0; kt < ntiles; kt++) {
        const int k0 = kt * 64;
        CP_WAIT(0);
        __syncthreads();

        if (kt + 1 < ntiles) {
            int stn = st ^ 1;
            #pragma unroll
            for (int l = 0; l < 4; l++) {
                int c = tid + l * 128;
                int rr = c >> 3;
                int ci = c & 7;
                cpa16(sK + (stn * KS_ST + rr * AT_PITCH + ci * 4) * 4,
                      Kp + (size_t)(k0 + 64 + rr) * HS + ci * 8);
                cpa16(sV + (stn * KS_ST + rr * AT_PITCH + ci * 4) * 4,
                      Vtp + (size_t)rr * Tn + k0 + 64 + ci * 8);
            }
            CP_COMMIT();
        }

        if (k0 <= qb + wrow + 31) {
            const uint32_t* Ks = KsB + st * KS_ST;
            const uint32_t* Vs = VsB + st * KS_ST;

            // ---- S = Q K^T ----
            float S[2][8][4];
            #pragma unroll
            for (int s = 0; s < 2; s++)
                #pragma unroll
                for (int nt = 0; nt < 8; nt++)
                    #pragma unroll
                    for (int r = 0; r < 4; r++) S[s][nt][r] = 0.f;

            #pragma unroll
            for (int kk = 0; kk < 4; kk++) {
                #pragma unroll
                for (int nt = 0; nt < 8; nt++) {
                    uint32_t b0 = Ks[(nt * 8 + gq) * AT_PITCH + kk * 8 + tq];
                    uint32_t b1 = Ks[(nt * 8 + gq) * AT_PITCH + kk * 8 + tq + 4];
                    mma_f16(S[0][nt], qf[0][kk][0], qf[0][kk][1], qf[0][kk][2], qf[0][kk][3], b0, b1);
                    mma_f16(S[1][nt], qf[1][kk][0], qf[1][kk][1], qf[1][kk][2], qf[1][kk][3], b0, b1);
                }
            }

            // ---- causal mask ----
            if (k0 + 63 > qb + wrow) {
                #pragma unroll
                for (int s = 0; s < 2; s++) {
                    int row0 = qb + wrow + 16 * s + gq;
                    #pragma unroll
                    for (int nt = 0; nt < 8; nt++) {
                        int col = k0 + nt * 8 + 2 * tq;
                        if (col     > row0)     S[s][nt][0] = -INFINITY;
                        if (col + 1 > row0)     S[s][nt][1] = -INFINITY;
                        if (col     > row0 + 8) S[s][nt][2] = -INFINITY;
                        if (col + 1 > row0 + 8) S[s][nt][3] = -INFINITY;
                    }
                }
            }

            // ---- online softmax; P packed directly into registers ----
            uint32_t Pr[2][8][2];
            #pragma unroll
            for (int s = 0; s < 2; s++) {
                float cm0 = -INFINITY, cm1 = -INFINITY;
                #pragma unroll
                for (int nt = 0; nt < 8; nt++) {
                    cm0 = fmaxf(cm0, fmaxf(S[s][nt][0], S[s][nt][1]));
                    cm1 = fmaxf(cm1, fmaxf(S[s][nt][2], S[s][nt][3]));
                }
                cm0 = fmaxf(cm0, __shfl_xor_sync(0xffffffff, cm0, 1));
                cm0 = fmaxf(cm0, __shfl_xor_sync(0xffffffff, cm0, 2));
                cm1 = fmaxf(cm1, __shfl_xor_sync(0xffffffff, cm1, 1));
                cm1 = fmaxf(cm1, __shfl_xor_sync(0xffffffff, cm1, 2));

                float mn0 = fmaxf(mrow[s][0], cm0);
                float mn1 = fmaxf(mrow[s][1], cm1);
                // Warp-uniform skip: if no row in this warp raised its max,
                // c0 == c1 == 1 and the rescale is a no-op (bit-identical).
                bool upd = (mn0 > mrow[s][0]) || (mn1 > mrow[s][1]);
                if (__any_sync(0xffffffff, upd)) {
                    float c0 = ex2(mrow[s][0] - mn0);
                    float c1 = ex2(mrow[s][1] - mn1);
                    lrow_[s][0] *= c0; lrow_[s][1] *= c1;
                    #pragma unroll
                    for (int nt = 0; nt < 8; nt++) {
                        O[s][nt][0] *= c0; O[s][nt][1] *= c0;
                        O[s][nt][2] *= c1; O[s][nt][3] *= c1;
                    }
                    mrow[s][0] = mn0; mrow[s][1] = mn1;
                }

                #pragma unroll
                for (int nt = 0; nt < 8; nt++) {
                    float p0 = ex2(S[s][nt][0] - mrow[s][0]);
                    float p1 = ex2(S[s][nt][1] - mrow[s][0]);
                    float p2 = ex2(S[s][nt][2] - mrow[s][1]);
                    float p3 = ex2(S[s][nt][3] - mrow[s][1]);
                    lrow_[s][0] += p0 + p1;
                    lrow_[s][1] += p2 + p3;
                    Pr[s][nt][0] = packh2(p0, p1);   // rows gq,   keys 8nt+2tq,+1
                    Pr[s][nt][1] = packh2(p2, p3);   // rows gq+8, keys 8nt+2tq,+1
                }
            }

            // ---- O += P V ---- (A frags = Pr directly; B = Vt[d][key] pairs)
            #pragma unroll
            for (int kk = 0; kk < 4; kk++) {
                #pragma unroll
                for (int nt = 0; nt < 8; nt++) {
                    uint32_t b0 = Vs[(nt * 8 + gq) * AT_PITCH + kk * 8 + tq];
                    uint32_t b1 = Vs[(nt * 8 + gq) * AT_PITCH + kk * 8 + tq + 4];
                    mma_f16(O[0][nt], Pr[0][2*kk][0], Pr[0][2*kk][1],
                            Pr[0][2*kk+1][0], Pr[0][2*kk+1][1], b0, b1);
                    mma_f16(O[1][nt], Pr[1][2*kk][0], Pr[1][2*kk][1],
                            Pr[1][2*kk+1][0], Pr[1][2*kk+1][1], b0, b1);
                }
            }
        }
        st ^= 1;
    }

    // ---- finalize: pack normalized O into fp16 A-tiles in g_ao ----
    const int bb = bh >> 4;
    const int h = bh & 15;
    __syncthreads();   // all warps done with Ps / mainloop
    #pragma unroll
    for (int s = 0; s < 2; s++) {
        float l0 = lrow_[s][0], l1 = lrow_[s][1];
        l0 += __shfl_xor_sync(0xffffffff, l0, 1);
        l0 += __shfl_xor_sync(0xffffffff, l0, 2);
        l1 += __shfl_xor_sync(0xffffffff, l1, 1);
        l1 += __shfl_xor_sync(0xffffffff, l1, 2);
        float inv0 = 1.f / l0;
        float inv1 = 1.f / l1;
        int m0l = wrow + 16 * s + gq;
        int m1l = m0l + 8;
        #pragma unroll
        for (int nt = 0; nt < 8; nt++) {
            int pg = nt * 4 + tq;          // col pair 0..31 within head
            int ktl = pg >> 4;             // local k-tile (d 0..31 / 32..63)
            int pin = pg & 15;
            Ps[ktl * 2048 + offA_h(m0l, pin)] = packh2(O[s][nt][0] * inv0, O[s][nt][1] * inv0);
            Ps[ktl * 2048 + offA_h(m1l, pin)] = packh2(O[s][nt][2] * inv1, O[s][nt][3] * inv1);
        }
    }
    __syncthreads();
    // store 2 tiles = 4096 words = 8192 halves = 1024 uint4; 8 per thread
    {
        __half* dst = g_ao + (((size_t)(bb * 16 + qt) * 32) + h * 2) * 4096;
        #pragma unroll
        for (int l = 0; l < 8; l++) {
            int i = tid + l * 128;        // 0..1023
            *(uint4*)&dst[(size_t)i * 8] = *(uint4*)&Ps[i * 4];
        }
    }
}

// ---------------------------------------------------------------------------
extern "C" void kernel_launch(void* const* d_in, const int* in_sizes, int n_in,
                              void* d_out, int out_size)
{
    const float* x      = (const float*)d_in[0];
    const float* w_kqv  = (const float*)d_in[1];
    const float* w_proj = (const float*)d_in[2];
    const float* b_proj = (const float*)d_in[3];
    float* out = (float*)d_out;

    cudaFuncSetAttribute(attn_mma, cudaFuncAttributeMaxDynamicSharedMemorySize, SMEM_ATTN);
    cudaFuncSetAttribute(gemm_f16<0>, cudaFuncAttributeMaxDynamicSharedMemorySize, 49152);
    cudaFuncSetAttribute(gemm_f16<1>, cudaFuncAttributeMaxDynamicSharedMemorySize, 49152);

    rope_init<<<64, 1024>>>();
    {
        dim3 gp(32, 96);             // fused: x (64) + w_kqv (24) + w_proj (8)
        pack_all<<<gp, 256>>>(x, w_kqv, w_proj);
    }

    dim3 g1(3*Dn/128, Mrows/128);   // 24 x 64
    gemm_f16<0><<<g1, 256, 49152>>>(nullptr, nullptr);

    dim3 g2(Tn/128, Bn*Hn);         // 16 x 64
    attn_mma<<<g2, 128, SMEM_ATTN>>>();

    dim3 g3(Dn/128, Mrows/128);     // 8 x 64
    gemm_f16<1><<<g3, 256, 49152>>>(b_proj, out);
}

// round 15
// speedup vs baseline: 1.1672x; 1.0231x over previous
#include <cuda_runtime.h>
#include <cuda_fp16.h>
#include <math.h>
#include <stdint.h>

// Problem constants
#define Bn 4
#define Tn 2048
#define Dn 1024
#define Hn 16
#define HS 64
#define Mrows (Bn*Tn)          // 8192

// Scratch (device globals; no runtime allocation allowed)
// g_q/g_k: [B,H,T,64] fp16, d-dimension PAIR-INTERLEAVED per 64-half row
// g_vt:    [B,H,64,T] fp16, t-dimension PAIR-INTERLEAVED per 64-key block
__device__ __half g_q [(size_t)Bn*Hn*Tn*HS];
__device__ __half g_k [(size_t)Bn*Hn*Tn*HS];
__device__ __half g_vt[(size_t)Bn*Hn*HS*Tn];
__device__ __half g_ao[(size_t)Mrows*Dn];      // attn out, packed fp16 A-tiles
__device__ float2 g_rope[Tn*32];               // (cos, sin) table
// fragment-major packed fp16 operands: [rowblk][ktile(32-k)][4096 halves]
__device__ __half g_xt[(size_t)Mrows*Dn];
__device__ __half g_wk[(size_t)3*Dn*Dn];
__device__ __half g_wp[(size_t)Dn*Dn];

// ---------------------------------------------------------------------------
// helpers
// ---------------------------------------------------------------------------
__device__ __forceinline__ float ex2(float x) {
    float y;
    asm("ex2.approx.f32 %0, %1;" : "=f"(y) : "f"(x));
    return y;
}

__device__ __forceinline__ void mma_f16(float c[4],
                                        uint32_t a0, uint32_t a1, uint32_t a2, uint32_t a3,
                                        uint32_t b0, uint32_t b1)
{
    asm volatile(
        "mma.sync.aligned.m16n8k16.row.col.f32.f16.f16.f32 "
        "{%0,%1,%2,%3}, {%4,%5,%6,%7}, {%8,%9}, {%0,%1,%2,%3};\n"
        : "+f"(c[0]), "+f"(c[1]), "+f"(c[2]), "+f"(c[3])
        : "r"(a0), "r"(a1), "r"(a2), "r"(a3), "r"(b0), "r"(b1));
}

__device__ __forceinline__ void cpa16(uint32_t dst_smem, const void* src) {
    asm volatile("cp.async.cg.shared.global [%0], [%1], 16;" :: "r"(dst_smem), "l"(src));
}
#define CP_COMMIT()  asm volatile("cp.async.commit_group;")
#define CP_WAIT(n)   asm volatile("cp.async.wait_group " #n ";")

__device__ __forceinline__ uint32_t packh2(float a, float b) {
    __half2 h = __floats2half2_rn(a, b);
    return *(uint32_t*)&h;
}

// pair-interleave permutation on 32-word blocks: word w=8kk+r ->
//   pos = (4kk+r)*2      if r<4
//   pos = (4kk+r-4)*2+1  if r>=4
// so the fragment pair (8kk+tq, 8kk+tq+4) becomes adjacent words.
__device__ __forceinline__ int permw(int w) {
    int kk = w >> 3;
    int r = w & 7;
    return (r < 4) ? (kk * 4 + r) * 2 : (kk * 4 + r - 4) * 2 + 1;
}

// word offset within a 128x32 fp16 tile (2048 words), p = k-pair 0..15
__device__ __forceinline__ int offA_h(int m, int p) {
    return (((((m >> 4) * 2 + (p >> 3)) * 8 + (m & 7)) * 4 + (p & 3)) * 4)
           + ((p >> 2) & 1) * 2 + ((m >> 3) & 1);
}
__device__ __forceinline__ int offB_h(int n, int p) {
    return (((((n >> 3) * 2 + (p >> 3)) * 8 + (n & 7)) * 4 + (p & 3)) * 2)
           + ((p >> 2) & 1);
}

// ---------------------------------------------------------------------------
// RoPE table init
// ---------------------------------------------------------------------------
__global__ void rope_init()
{
    int idx = blockIdx.x * blockDim.x + threadIdx.x;
    int t = idx >> 5;
    int i = idx & 31;
    float theta = powf(10000.0f, (float)i * (-2.0f / 64.0f));
    float ang = (float)t * theta;
    float sn, cs;
    sincosf(ang, &sn, &cs);
    g_rope[idx] = make_float2(cs, sn);
}

// ---------------------------------------------------------------------------
// Pack ALL THREE operands in one launch. grid = (32, 96).
// ---------------------------------------------------------------------------
__global__ void __launch_bounds__(256) pack_all(const float* __restrict__ x,
                                                const float* __restrict__ wk,
                                                const float* __restrict__ wp)
{
    __shared__ __align__(16) __half sm[4096];
    const int by = blockIdx.y;
    int sel, mblk;
    const float* src;
    if (by < 64)      { sel = 0; mblk = by;      src = x;  }
    else if (by < 88) { sel = 1; mblk = by - 64; src = wk; }
    else              { sel = 2; mblk = by - 88; src = wp; }
    __half* dst = (sel == 0) ? g_xt : (sel == 1) ? g_wk : g_wp;
    const bool isA = (sel == 0);

    const int k0 = blockIdx.x * 32;
    const int m0 = mblk * 128;
    const int tid = threadIdx.x;

    #pragma unroll
    for (int l = 0; l < 4; l++) {
        int idx = tid + l * 256;
        int row = idx >> 3;
        int c4 = (idx & 7) * 4;
        float4 v = *(const float4*)(src + (size_t)(m0 + row) * 1024 + k0 + c4);
        int p = c4 >> 1;
        __half2 w0 = __floats2half2_rn(v.x, v.y);
        __half2 w1 = __floats2half2_rn(v.z, v.w);
        int o0 = isA ? offA_h(row, p)     : offB_h(row, p);
        int o1 = isA ? offA_h(row, p + 1) : offB_h(row, p + 1);
        *(__half2*)&sm[o0 * 2] = w0;
        *(__half2*)&sm[o1 * 2] = w1;
    }
    __syncthreads();
    size_t gb = ((size_t)mblk * 32 + blockIdx.x) * 4096;
    #pragma unroll
    for (int l = 0; l < 2; l++) {
        int i = tid + l * 256;
        *(uint4*)&dst[gb + (size_t)i * 8] = *(uint4*)&sm[i * 8];
    }
}

// ---------------------------------------------------------------------------
// fp16 tensor-core GEMM on PACKED operands: C[M,N] = A @ W^T, K=1024.
// MODE 0: QKV epilogue writes PAIR-INTERLEAVED g_q/g_k/g_vt.
// MODE 1: proj epilogue (bias -> out), A = g_ao.
// ---------------------------------------------------------------------------
template<int MODE>
__global__ void __launch_bounds__(256) gemm_f16(const float* __restrict__ bias,
                                                float* __restrict__ out)
{
    extern __shared__ __align__(16) uint32_t gsm[];
    uint32_t* As = gsm;            // [3][2048 words]
    uint32_t* Ws = gsm + 3 * 2048;

    const int m0 = blockIdx.y * 128;
    const int n0 = blockIdx.x * 128;
    const int tid = threadIdx.x;
    const int wid = tid >> 5;
    const int lane = tid & 31;
    const int wm = wid >> 2;
    const int wn = wid & 3;
    const int gq = lane >> 2;
    const int tq = lane & 3;

    const __half* Abase = (MODE == 1) ? g_ao : g_xt;
    const __half* Wbase = (MODE == 1) ? g_wp : g_wk;
    const __half* Atiles = Abase + (size_t)blockIdx.y * 32 * 4096;
    const __half* Wtiles = Wbase + (size_t)blockIdx.x * 32 * 4096;

    const uint32_t sA = (uint32_t)__cvta_generic_to_shared(As);
    const uint32_t sW = (uint32_t)__cvta_generic_to_shared(Ws);

    float acc[4][4][4];
    #pragma unroll
    for (int mt = 0; mt < 4; mt++)
        #pragma unroll
        for (int nt = 0; nt < 4; nt++)
            #pragma unroll
            for (int r = 0; r < 4; r++) acc[mt][nt][r] = 0.f;

    #pragma unroll
    for (int p = 0; p < 2; p++) {
        cpa16(sA + (p * 2048 + tid * 8 + 0) * 4, Atiles + (size_t)p * 4096 + tid * 16 + 0);
        cpa16(sA + (p * 2048 + tid * 8 + 4) * 4, Atiles + (size_t)p * 4096 + tid * 16 + 8);
        cpa16(sW + (p * 2048 + tid * 8 + 0) * 4, Wtiles + (size_t)p * 4096 + tid * 16 + 0);
        cpa16(sW + (p * 2048 + tid * 8 + 4) * 4, Wtiles + (size_t)p * 4096 + tid * 16 + 8);
        CP_COMMIT();
    }

    int st = 0;
    for (int kt = 0; kt < 32; kt++) {
        if (kt < 31) { CP_WAIT(1); } else { CP_WAIT(0); }
        __syncthreads();

        if (kt + 2 < 32) {
            int stn = st + 2; if (stn >= 3) stn -= 3;
            const __half* At = Atiles + (size_t)(kt + 2) * 4096;
            const __half* Wt = Wtiles + (size_t)(kt + 2) * 4096;
            cpa16(sA + (stn * 2048 + tid * 8 + 0) * 4, At + tid * 16 + 0);
            cpa16(sA + (stn * 2048 + tid * 8 + 4) * 4, At + tid * 16 + 8);
            cpa16(sW + (stn * 2048 + tid * 8 + 0) * 4, Wt + tid * 16 + 0);
            cpa16(sW + (stn * 2048 + tid * 8 + 4) * 4, Wt + tid * 16 + 8);
            CP_COMMIT();
        }

        const uint32_t* Acur = As + st * 2048;
        const uint32_t* Wcur = Ws + st * 2048;
        #pragma unroll
        for (int ks = 0; ks < 2; ks++) {
            uint4 af[4];
            uint2 bf[4];
            #pragma unroll
            for (int mt = 0; mt < 4; mt++)
                af[mt] = *(const uint4*)&Acur[((((wm * 4 + mt) * 2 + ks) * 8 + gq) * 4 + tq) * 4];
            #pragma unroll
            for (int nt = 0; nt < 4; nt++)
                bf[nt] = *(const uint2*)&Wcur[((((wn * 4 + nt) * 2 + ks) * 8 + gq) * 4 + tq) * 2];
            #pragma unroll
            for (int mt = 0; mt < 4; mt++)
                #pragma unroll
                for (int nt = 0; nt < 4; nt++)
                    mma_f16(acc[mt][nt], af[mt].x, af[mt].y, af[mt].z, af[mt].w,
                            bf[nt].x, bf[nt].y);
        }
        st = (st == 2) ? 0 : st + 1;
    }

    if (MODE == 0) {
        const float QSC = 0.125f * 1.4426950408889634f;  // scale * log2(e)
        #pragma unroll
        for (int mt = 0; mt < 4; mt++) {
            #pragma unroll
            for (int r = 0; r < 2; r++) {
                int m = m0 + wm * 64 + mt * 16 + gq + r * 8;
                int bb = m >> 11;
                int tt = m & 2047;
                #pragma unroll
                for (int nt = 0; nt < 4; nt++) {
                    int col = n0 + wn * 32 + nt * 8 + 2 * tq;
                    int which = col >> 10;
                    int rem = col & 1023;
                    int h = rem >> 6;
                    int d = rem & 63;        // even
                    int bh = bb * Hn + h;
                    float e = acc[mt][nt][r * 2 + 0];
                    float o = acc[mt][nt][r * 2 + 1];
                    if (which == 2) {
                        // Vt: rows d,d+1; column tt permuted within 64-block
                        int u = tt & 63;
                        int colp = (tt & ~63) + 2 * permw(u >> 1) + (u & 1);
                        size_t vo = ((size_t)bh * HS + d) * Tn + colp;
                        g_vt[vo]      = __float2half_rn(e);
                        g_vt[vo + Tn] = __float2half_rn(o);
                    } else {
                        float2 cs = g_rope[tt * 32 + (d >> 1)];
                        float t1 = e * cs.x - o * cs.y;
                        float t2 = e * cs.y + o * cs.x;
                        // d permuted within row: word d>>1 -> permw
                        size_t off = ((size_t)bh * Tn + tt) * HS + 2 * permw(d >> 1);
                        if (which == 0) {
                            *(__half2*)(g_k + off) = __floats2half2_rn(t1, t2);
                        } else {
                            *(__half2*)(g_q + off) = __floats2half2_rn(t1 * QSC, t2 * QSC);
                        }
                    }
                }
            }
        }
    } else {
        #pragma unroll
        for (int mt = 0; mt < 4; mt++) {
            #pragma unroll
            for (int r = 0; r < 2; r++) {
                int m = m0 + wm * 64 + mt * 16 + gq + r * 8;
                #pragma unroll
                for (int nt = 0; nt < 4; nt++) {
                    int col = n0 + wn * 32 + nt * 8 + 2 * tq;
                    float2 v2;
                    v2.x = acc[mt][nt][r * 2 + 0] + bias[col + 0];
                    v2.y = acc[mt][nt][r * 2 + 1] + bias[col + 1];
                    *(float2*)(out + (size_t)m * 1024 + col) = v2;
                }
            }
        }
    }
}

// ---------------------------------------------------------------------------
// fp16 tensor-core causal flash attention (mma m16n8k16), m32 warp tiles.
// Operands pair-interleaved -> every B fragment and Q fragment is ONE LDS.64.
// Pitch 40 words: conflict-free for the LDS.64 pattern (banks 8gq+2tq+{0,1}).
// P in registers; warp-uniform rescale skip. 2-stage cp.async K/Vt pipeline.
// Epilogue packs fp16 A-tiles into g_ao. grid = (16, 64).
// ---------------------------------------------------------------------------
#define AT_PITCH 40                       // words per 64-half row
#define KS_ST (64*AT_PITCH)               // 2560 words per stage
#define SMEM_ATTN ((2*KS_ST*2 + 128*AT_PITCH) * 4)   // 61440 bytes

__global__ void __launch_bounds__(128, 2) attn_mma()
{
    extern __shared__ __align__(16) uint32_t smw[];
    uint32_t* KsB = smw;                  // [2][64][40]
    uint32_t* VsB = KsB + 2 * KS_ST;      // [2][64][40]
    uint32_t* Ps  = VsB + 2 * KS_ST;      // [128][40]  Q staging / O packing

    const int bh = blockIdx.y;
    const int qt = gridDim.x - 1 - blockIdx.x;   // heavy blocks first
    const int tid = threadIdx.x;
    const int wid = tid >> 5;
    const int lane = tid & 31;
    const int gq = lane >> 2;
    const int tq = lane & 3;
    const int qb = qt * 128;
    const int wrow = wid * 32;

    const __half* Qp = g_q + (size_t)bh * Tn * HS;
    const __half* Kp = g_k + (size_t)bh * Tn * HS;
    const __half* Vtp = g_vt + (size_t)bh * HS * Tn;

    const uint32_t sK = (uint32_t)__cvta_generic_to_shared(KsB);
    const uint32_t sV = (uint32_t)__cvta_generic_to_shared(VsB);

    // K/Vt staging: 64 rows x 8 chunks(16B); 512 chunks / 128 thr = 4 each
    #pragma unroll
    for (int l = 0; l < 4; l++) {
        int c = tid + l * 128;
        int rr = c >> 3;
        int ci = c & 7;
        cpa16(sK + (rr * AT_PITCH + ci * 4) * 4, Kp + (size_t)rr * HS + ci * 8);
        cpa16(sV + (rr * AT_PITCH + ci * 4) * 4, Vtp + (size_t)rr * Tn + ci * 8);
    }
    CP_COMMIT();

    // stage Q (128 rows x 8 chunks)
    #pragma unroll
    for (int l = 0; l < 8; l++) {
        int c = tid + l * 128;
        int rr = c >> 3;
        int ci = c & 7;
        uint4 v = *(const uint4*)(Qp + (size_t)(qb + rr) * HS + ci * 8);
        *(uint4*)&Ps[rr * AT_PITCH + ci * 4] = v;
    }
    __syncthreads();

    int roff[2][2];
    #pragma unroll
    for (int s = 0; s < 2; s++) {
        roff[s][0] = (wrow + 16 * s + gq) * AT_PITCH;
        roff[s][1] = (wrow + 16 * s + gq + 8) * AT_PITCH;
    }

    // Q fragments via LDS.64 on pair-interleaved layout
    uint32_t qf[2][4][4];
    #pragma unroll
    for (int s = 0; s < 2; s++)
        #pragma unroll
        for (int kk = 0; kk < 4; kk++) {
            uint2 l0 = *(const uint2*)&Ps[roff[s][0] + (kk * 4 + tq) * 2];
            uint2 l1 = *(const uint2*)&Ps[roff[s][1] + (kk * 4 + tq) * 2];
            qf[s][kk][0] = l0.x;  // word 8kk+tq
            qf[s][kk][2] = l0.y;  // word 8kk+tq+4
            qf[s][kk][1] = l1.x;
            qf[s][kk][3] = l1.y;
        }

    float O[2][8][4];
    #pragma unroll
    for (int s = 0; s < 2; s++)
        #pragma unroll
        for (int nt = 0; nt < 8; nt++)
            #pragma unroll
            for (int r = 0; r < 4; r++) O[s][nt][r] = 0.f;
    float mrow[2][2], lrow_[2][2];
    #pragma unroll
    for (int s = 0; s < 2; s++) {
        mrow[s][0] = -INFINITY; mrow[s][1] = -INFINITY;
        lrow_[s][0] = 0.f;      lrow_[s][1] = 0.f;
    }

    const int ntiles = 2 * qt + 2;
    int st = 0;
    for (int kt = 0; kt < ntiles; kt++) {
        const int k0 = kt * 64;
        CP_WAIT(0);
        __syncthreads();

        if (kt + 1 < ntiles) {
            int stn = st ^ 1;
            #pragma unroll
            for (int l = 0; l < 4; l++) {
                int c = tid + l * 128;
                int rr = c >> 3;
                int ci = c & 7;
                cpa16(sK + (stn * KS_ST + rr * AT_PITCH + ci * 4) * 4,
                      Kp + (size_t)(k0 + 64 + rr) * HS + ci * 8);
                cpa16(sV + (stn * KS_ST + rr * AT_PITCH + ci * 4) * 4,
                      Vtp + (size_t)rr * Tn + k0 + 64 + ci * 8);
            }
            CP_COMMIT();
        }

        if (k0 <= qb + wrow + 31) {
            const uint32_t* Ks = KsB + st * KS_ST;
            const uint32_t* Vs = VsB + st * KS_ST;

            // ---- S = Q K^T ---- (B frag = one LDS.64)
            float S[2][8][4];
            #pragma unroll
            for (int s = 0; s < 2; s++)
                #pragma unroll
                for (int nt = 0; nt < 8; nt++)
                    #pragma unroll
                    for (int r = 0; r < 4; r++) S[s][nt][r] = 0.f;

            #pragma unroll
            for (int kk = 0; kk < 4; kk++) {
                #pragma unroll
                for (int nt = 0; nt < 8; nt++) {
                    uint2 b = *(const uint2*)&Ks[(nt * 8 + gq) * AT_PITCH + (kk * 4 + tq) * 2];
                    mma_f16(S[0][nt], qf[0][kk][0], qf[0][kk][1], qf[0][kk][2], qf[0][kk][3], b.x, b.y);
                    mma_f16(S[1][nt], qf[1][kk][0], qf[1][kk][1], qf[1][kk][2], qf[1][kk][3], b.x, b.y);
                }
            }

            // ---- causal mask ----
            if (k0 + 63 > qb + wrow) {
                #pragma unroll
                for (int s = 0; s < 2; s++) {
                    int row0 = qb + wrow + 16 * s + gq;
                    #pragma unroll
                    for (int nt = 0; nt < 8; nt++) {
                        int col = k0 + nt * 8 + 2 * tq;
                        if (col     > row0)     S[s][nt][0] = -INFINITY;
                        if (col + 1 > row0)     S[s][nt][1] = -INFINITY;
                        if (col     > row0 + 8) S[s][nt][2] = -INFINITY;
                        if (col + 1 > row0 + 8) S[s][nt][3] = -INFINITY;
                    }
                }
            }

            // ---- online softmax; P packed directly into registers ----
            uint32_t Pr[2][8][2];
            #pragma unroll
            for (int s = 0; s < 2; s++) {
                float cm0 = -INFINITY, cm1 = -INFINITY;
                #pragma unroll
                for (int nt = 0; nt < 8; nt++) {
                    cm0 = fmaxf(cm0, fmaxf(S[s][nt][0], S[s][nt][1]));
                    cm1 = fmaxf(cm1, fmaxf(S[s][nt][2], S[s][nt][3]));
                }
                cm0 = fmaxf(cm0, __shfl_xor_sync(0xffffffff, cm0, 1));
                cm0 = fmaxf(cm0, __shfl_xor_sync(0xffffffff, cm0, 2));
                cm1 = fmaxf(cm1, __shfl_xor_sync(0xffffffff, cm1, 1));
                cm1 = fmaxf(cm1, __shfl_xor_sync(0xffffffff, cm1, 2));

                float mn0 = fmaxf(mrow[s][0], cm0);
                float mn1 = fmaxf(mrow[s][1], cm1);
                bool upd = (mn0 > mrow[s][0]) || (mn1 > mrow[s][1]);
                if (__any_sync(0xffffffff, upd)) {
                    float c0 = ex2(mrow[s][0] - mn0);
                    float c1 = ex2(mrow[s][1] - mn1);
                    lrow_[s][0] *= c0; lrow_[s][1] *= c1;
                    #pragma unroll
                    for (int nt = 0; nt < 8; nt++) {
                        O[s][nt][0] *= c0; O[s][nt][1] *= c0;
                        O[s][nt][2] *= c1; O[s][nt][3] *= c1;
                    }
                    mrow[s][0] = mn0; mrow[s][1] = mn1;
                }

                #pragma unroll
                for (int nt = 0; nt < 8; nt++) {
                    float p0 = ex2(S[s][nt][0] - mrow[s][0]);
                    float p1 = ex2(S[s][nt][1] - mrow[s][0]);
                    float p2 = ex2(S[s][nt][2] - mrow[s][1]);
                    float p3 = ex2(S[s][nt][3] - mrow[s][1]);
                    lrow_[s][0] += p0 + p1;
                    lrow_[s][1] += p2 + p3;
                    Pr[s][nt][0] = packh2(p0, p1);
                    Pr[s][nt][1] = packh2(p2, p3);
                }
            }

            // ---- O += P V ---- (B frag = one LDS.64 on permuted Vt)
            #pragma unroll
            for (int kk = 0; kk < 4; kk++) {
                #pragma unroll
                for (int nt = 0; nt < 8; nt++) {
                    uint2 b = *(const uint2*)&Vs[(nt * 8 + gq) * AT_PITCH + (kk * 4 + tq) * 2];
                    mma_f16(O[0][nt], Pr[0][2*kk][0], Pr[0][2*kk][1],
                            Pr[0][2*kk+1][0], Pr[0][2*kk+1][1], b.x, b.y);
                    mma_f16(O[1][nt], Pr[1][2*kk][0], Pr[1][2*kk][1],
                            Pr[1][2*kk+1][0], Pr[1][2*kk+1][1], b.x, b.y);
                }
            }
        }
        st ^= 1;
    }

    // ---- finalize: pack normalized O into fp16 A-tiles in g_ao ----
    const int bb = bh >> 4;
    const int h = bh & 15;
    __syncthreads();
    #pragma unroll
    for (int s = 0; s < 2; s++) {
        float l0 = lrow_[s][0], l1 = lrow_[s][1];
        l0 += __shfl_xor_sync(0xffffffff, l0, 1);
        l0 += __shfl_xor_sync(0xffffffff, l0, 2);
        l1 += __shfl_xor_sync(0xffffffff, l1, 1);
        l1 += __shfl_xor_sync(0xffffffff, l1, 2);
        float inv0 = 1.f / l0;
        float inv1 = 1.f / l1;
        int m0l = wrow + 16 * s + gq;
        int m1l = m0l + 8;
        #pragma unroll
        for (int nt = 0; nt < 8; nt++) {
            int pg = nt * 4 + tq;
            int ktl = pg >> 4;
            int pin = pg & 15;
            Ps[ktl * 2048 + offA_h(m0l, pin)] = packh2(O[s][nt][0] * inv0, O[s][nt][1] * inv0);
            Ps[ktl * 2048 + offA_h(m1l, pin)] = packh2(O[s][nt][2] * inv1, O[s][nt][3] * inv1);
        }
    }
    __syncthreads();
    {
        __half* dst = g_ao + (((size_t)(bb * 16 + qt) * 32) + h * 2) * 4096;
        #pragma unroll
        for (int l = 0; l < 8; l++) {
            int i = tid + l * 128;
            *(uint4*)&dst[(size_t)i * 8] = *(uint4*)&Ps[i * 4];
        }
    }
}

// ---------------------------------------------------------------------------
extern "C" void kernel_launch(void* const* d_in, const int* in_sizes, int n_in,
                              void* d_out, int out_size)
{
    const float* x      = (const float*)d_in[0];
    const float* w_kqv  = (const float*)d_in[1];
    const float* w_proj = (const float*)d_in[2];
    const float* b_proj = (const float*)d_in[3];
    float* out = (float*)d_out;

    cudaFuncSetAttribute(attn_mma, cudaFuncAttributeMaxDynamicSharedMemorySize, SMEM_ATTN);
    cudaFuncSetAttribute(gemm_f16<0>, cudaFuncAttributeMaxDynamicSharedMemorySize, 49152);
    cudaFuncSetAttribute(gemm_f16<1>, cudaFuncAttributeMaxDynamicSharedMemorySize, 49152);

    rope_init<<<64, 1024>>>();
    {
        dim3 gp(32, 96);
        pack_all<<<gp, 256>>>(x, w_kqv, w_proj);
    }

    dim3 g1(3*Dn/128, Mrows/128);   // 24 x 64
    gemm_f16<0><<<g1, 256, 49152>>>(nullptr, nullptr);

    dim3 g2(Tn/128, Bn*Hn);         // 16 x 64
    attn_mma<<<g2, 128, SMEM_ATTN>>>();

    dim3 g3(Dn/128, Mrows/128);     // 8 x 64
    gemm_f16<1><<<g3, 256, 49152>>>(b_proj, out);
}

// round 16
// speedup vs baseline: 1.1739x; 1.0057x over previous
#include <cuda_runtime.h>
#include <cuda_fp16.h>
#include <math.h>
#include <stdint.h>

// Problem constants
#define Bn 4
#define Tn 2048
#define Dn 1024
#define Hn 16
#define HS 64
#define Mrows (Bn*Tn)          // 8192

// Scratch (device globals; no runtime allocation allowed)
// g_q/g_k: [B,H,T,64] fp16, d-dimension PAIR-INTERLEAVED per 64-half row
// g_vt:    [B,H,64,T] fp16, t-dimension PAIR-INTERLEAVED per 64-key block
__device__ __half g_q [(size_t)Bn*Hn*Tn*HS];
__device__ __half g_k [(size_t)Bn*Hn*Tn*HS];
__device__ __half g_vt[(size_t)Bn*Hn*HS*Tn];
__device__ __half g_ao[(size_t)Mrows*Dn];      // attn out, packed fp16 A-tiles
__device__ float2 g_rope[Tn*32];               // (cos, sin) table
// fragment-major packed fp16 operands: [rowblk][ktile(32-k)][4096 halves]
__device__ __half g_xt[(size_t)Mrows*Dn];
__device__ __half g_wk[(size_t)3*Dn*Dn];
__device__ __half g_wp[(size_t)Dn*Dn];

// ---------------------------------------------------------------------------
// helpers
// ---------------------------------------------------------------------------
__device__ __forceinline__ float ex2(float x) {
    float y;
    asm("ex2.approx.f32 %0, %1;" : "=f"(y) : "f"(x));
    return y;
}

__device__ __forceinline__ void mma_f16(float c[4],
                                        uint32_t a0, uint32_t a1, uint32_t a2, uint32_t a3,
                                        uint32_t b0, uint32_t b1)
{
    asm volatile(
        "mma.sync.aligned.m16n8k16.row.col.f32.f16.f16.f32 "
        "{%0,%1,%2,%3}, {%4,%5,%6,%7}, {%8,%9}, {%0,%1,%2,%3};\n"
        : "+f"(c[0]), "+f"(c[1]), "+f"(c[2]), "+f"(c[3])
        : "r"(a0), "r"(a1), "r"(a2), "r"(a3), "r"(b0), "r"(b1));
}

__device__ __forceinline__ void cpa16(uint32_t dst_smem, const void* src) {
    asm volatile("cp.async.cg.shared.global [%0], [%1], 16;" :: "r"(dst_smem), "l"(src));
}
#define CP_COMMIT()  asm volatile("cp.async.commit_group;")
#define CP_WAIT(n)   asm volatile("cp.async.wait_group " #n ";")

__device__ __forceinline__ uint32_t packh2(float a, float b) {
    __half2 h = __floats2half2_rn(a, b);
    return *(uint32_t*)&h;
}

// pair-interleave permutation on 32-word blocks: word w=8kk+r ->
//   pos = (4kk+r)*2 if r<4 else (4kk+r-4)*2+1
// so the fragment pair (8kk+tq, 8kk+tq+4) becomes adjacent words.
__device__ __forceinline__ int permw(int w) {
    int kk = w >> 3;
    int r = w & 7;
    return (r < 4) ? (kk * 4 + r) * 2 : (kk * 4 + r - 4) * 2 + 1;
}

// word offset within a 128x32 fp16 tile (2048 words), p = k-pair 0..15
__device__ __forceinline__ int offA_h(int m, int p) {
    return (((((m >> 4) * 2 + (p >> 3)) * 8 + (m & 7)) * 4 + (p & 3)) * 4)
           + ((p >> 2) & 1) * 2 + ((m >> 3) & 1);
}
__device__ __forceinline__ int offB_h(int n, int p) {
    return (((((n >> 3) * 2 + (p >> 3)) * 8 + (n & 7)) * 4 + (p & 3)) * 2)
           + ((p >> 2) & 1);
}

// ---------------------------------------------------------------------------
// RoPE table init
// ---------------------------------------------------------------------------
__global__ void rope_init()
{
    int idx = blockIdx.x * blockDim.x + threadIdx.x;
    int t = idx >> 5;
    int i = idx & 31;
    float theta = powf(10000.0f, (float)i * (-2.0f / 64.0f));
    float ang = (float)t * theta;
    float sn, cs;
    sincosf(ang, &sn, &cs);
    g_rope[idx] = make_float2(cs, sn);
}

// ---------------------------------------------------------------------------
// Pack ALL THREE operands in one launch. grid = (32, 96).
// ---------------------------------------------------------------------------
__global__ void __launch_bounds__(256) pack_all(const float* __restrict__ x,
                                                const float* __restrict__ wk,
                                                const float* __restrict__ wp)
{
    __shared__ __align__(16) __half sm[4096];
    const int by = blockIdx.y;
    int sel, mblk;
    const float* src;
    if (by < 64)      { sel = 0; mblk = by;      src = x;  }
    else if (by < 88) { sel = 1; mblk = by - 64; src = wk; }
    else              { sel = 2; mblk = by - 88; src = wp; }
    __half* dst = (sel == 0) ? g_xt : (sel == 1) ? g_wk : g_wp;
    const bool isA = (sel == 0);

    const int k0 = blockIdx.x * 32;
    const int m0 = mblk * 128;
    const int tid = threadIdx.x;

    #pragma unroll
    for (int l = 0; l < 4; l++) {
        int idx = tid + l * 256;
        int row = idx >> 3;
        int c4 = (idx & 7) * 4;
        float4 v = *(const float4*)(src + (size_t)(m0 + row) * 1024 + k0 + c4);
        int p = c4 >> 1;
        __half2 w0 = __floats2half2_rn(v.x, v.y);
        __half2 w1 = __floats2half2_rn(v.z, v.w);
        int o0 = isA ? offA_h(row, p)     : offB_h(row, p);
        int o1 = isA ? offA_h(row, p + 1) : offB_h(row, p + 1);
        *(__half2*)&sm[o0 * 2] = w0;
        *(__half2*)&sm[o1 * 2] = w1;
    }
    __syncthreads();
    size_t gb = ((size_t)mblk * 32 + blockIdx.x) * 4096;
    #pragma unroll
    for (int l = 0; l < 2; l++) {
        int i = tid + l * 256;
        *(uint4*)&dst[gb + (size_t)i * 8] = *(uint4*)&sm[i * 8];
    }
}

// ---------------------------------------------------------------------------
// fp16 tensor-core GEMM on PACKED operands: C[M,N] = A @ W^T, K=1024.
// MODE 0: QKV epilogue writes PAIR-INTERLEAVED g_q/g_k/g_vt.
// MODE 1: proj epilogue (bias -> out), A = g_ao.
// ---------------------------------------------------------------------------
template<int MODE>
__global__ void __launch_bounds__(256) gemm_f16(const float* __restrict__ bias,
                                                float* __restrict__ out)
{
    extern __shared__ __align__(16) uint32_t gsm[];
    uint32_t* As = gsm;            // [3][2048 words]
    uint32_t* Ws = gsm + 3 * 2048;

    const int m0 = blockIdx.y * 128;
    const int n0 = blockIdx.x * 128;
    const int tid = threadIdx.x;
    const int wid = tid >> 5;
    const int lane = tid & 31;
    const int wm = wid >> 2;
    const int wn = wid & 3;
    const int gq = lane >> 2;
    const int tq = lane & 3;

    const __half* Abase = (MODE == 1) ? g_ao : g_xt;
    const __half* Wbase = (MODE == 1) ? g_wp : g_wk;
    const __half* Atiles = Abase + (size_t)blockIdx.y * 32 * 4096;
    const __half* Wtiles = Wbase + (size_t)blockIdx.x * 32 * 4096;

    const uint32_t sA = (uint32_t)__cvta_generic_to_shared(As);
    const uint32_t sW = (uint32_t)__cvta_generic_to_shared(Ws);

    float acc[4][4][4];
    #pragma unroll
    for (int mt = 0; mt < 4; mt++)
        #pragma unroll
        for (int nt = 0; nt < 4; nt++)
            #pragma unroll
            for (int r = 0; r < 4; r++) acc[mt][nt][r] = 0.f;

    #pragma unroll
    for (int p = 0; p < 2; p++) {
        cpa16(sA + (p * 2048 + tid * 8 + 0) * 4, Atiles + (size_t)p * 4096 + tid * 16 + 0);
        cpa16(sA + (p * 2048 + tid * 8 + 4) * 4, Atiles + (size_t)p * 4096 + tid * 16 + 8);
        cpa16(sW + (p * 2048 + tid * 8 + 0) * 4, Wtiles + (size_t)p * 4096 + tid * 16 + 0);
        cpa16(sW + (p * 2048 + tid * 8 + 4) * 4, Wtiles + (size_t)p * 4096 + tid * 16 + 8);
        CP_COMMIT();
    }

    int st = 0;
    for (int kt = 0; kt < 32; kt++) {
        if (kt < 31) { CP_WAIT(1); } else { CP_WAIT(0); }
        __syncthreads();

        if (kt + 2 < 32) {
            int stn = st + 2; if (stn >= 3) stn -= 3;
            const __half* At = Atiles + (size_t)(kt + 2) * 4096;
            const __half* Wt = Wtiles + (size_t)(kt + 2) * 4096;
            cpa16(sA + (stn * 2048 + tid * 8 + 0) * 4, At + tid * 16 + 0);
            cpa16(sA + (stn * 2048 + tid * 8 + 4) * 4, At + tid * 16 + 8);
            cpa16(sW + (stn * 2048 + tid * 8 + 0) * 4, Wt + tid * 16 + 0);
            cpa16(sW + (stn * 2048 + tid * 8 + 4) * 4, Wt + tid * 16 + 8);
            CP_COMMIT();
        }

        const uint32_t* Acur = As + st * 2048;
        const uint32_t* Wcur = Ws + st * 2048;
        #pragma unroll
        for (int ks = 0; ks < 2; ks++) {
            uint4 af[4];
            uint2 bf[4];
            #pragma unroll
            for (int mt = 0; mt < 4; mt++)
                af[mt] = *(const uint4*)&Acur[((((wm * 4 + mt) * 2 + ks) * 8 + gq) * 4 + tq) * 4];
            #pragma unroll
            for (int nt = 0; nt < 4; nt++)
                bf[nt] = *(const uint2*)&Wcur[((((wn * 4 + nt) * 2 + ks) * 8 + gq) * 4 + tq) * 2];
            #pragma unroll
            for (int mt = 0; mt < 4; mt++)
                #pragma unroll
                for (int nt = 0; nt < 4; nt++)
                    mma_f16(acc[mt][nt], af[mt].x, af[mt].y, af[mt].z, af[mt].w,
                            bf[nt].x, bf[nt].y);
        }
        st = (st == 2) ? 0 : st + 1;
    }

    if (MODE == 0) {
        const float QSC = 0.125f * 1.4426950408889634f;  // scale * log2(e)
        #pragma unroll
        for (int mt = 0; mt < 4; mt++) {
            #pragma unroll
            for (int r = 0; r < 2; r++) {
                int m = m0 + wm * 64 + mt * 16 + gq + r * 8;
                int bb = m >> 11;
                int tt = m & 2047;
                #pragma unroll
                for (int nt = 0; nt < 4; nt++) {
                    int col = n0 + wn * 32 + nt * 8 + 2 * tq;
                    int which = col >> 10;
                    int rem = col & 1023;
                    int h = rem >> 6;
                    int d = rem & 63;        // even
                    int bh = bb * Hn + h;
                    float e = acc[mt][nt][r * 2 + 0];
                    float o = acc[mt][nt][r * 2 + 1];
                    if (which == 2) {
                        int u = tt & 63;
                        int colp = (tt & ~63) + 2 * permw(u >> 1) + (u & 1);
                        size_t vo = ((size_t)bh * HS + d) * Tn + colp;
                        g_vt[vo]      = __float2half_rn(e);
                        g_vt[vo + Tn] = __float2half_rn(o);
                    } else {
                        float2 cs = g_rope[tt * 32 + (d >> 1)];
                        float t1 = e * cs.x - o * cs.y;
                        float t2 = e * cs.y + o * cs.x;
                        size_t off = ((size_t)bh * Tn + tt) * HS + 2 * permw(d >> 1);
                        if (which == 0) {
                            *(__half2*)(g_k + off) = __floats2half2_rn(t1, t2);
                        } else {
                            *(__half2*)(g_q + off) = __floats2half2_rn(t1 * QSC, t2 * QSC);
                        }
                    }
                }
            }
        }
    } else {
        #pragma unroll
        for (int mt = 0; mt < 4; mt++) {
            #pragma unroll
            for (int r = 0; r < 2; r++) {
                int m = m0 + wm * 64 + mt * 16 + gq + r * 8;
                #pragma unroll
                for (int nt = 0; nt < 4; nt++) {
                    int col = n0 + wn * 32 + nt * 8 + 2 * tq;
                    float2 v2;
                    v2.x = acc[mt][nt][r * 2 + 0] + bias[col + 0];
                    v2.y = acc[mt][nt][r * 2 + 1] + bias[col + 1];
                    *(float2*)(out + (size_t)m * 1024 + col) = v2;
                }
            }
        }
    }
}

// ---------------------------------------------------------------------------
// fp16 tensor-core causal flash attention, m16 warp tiles, 3 CTAs/SM.
// Block: 64 q-rows, 4 warps x m16, 128 threads. Natural regs ~150 < 170 cap.
// Pair-interleaved operands -> LDS.64 fragments; P in registers.
// Per-row arithmetic identical to round-15 kernel (bit-identical output).
// Epilogue packs this block's 64 rows into the matching HALF of each
// 2048-word A-tile (offA_h(m+64,p) == offA_h(m,p)+1024).
// grid = (32, 64); heavy q-blocks first.
// ---------------------------------------------------------------------------
#define AT_PITCH 40                       // words per 64-half row
#define KS_ST (64*AT_PITCH)               // 2560 words per K/V stage
#define SMEM_ATTN ((2*KS_ST*2 + 64*AT_PITCH) * 4)   // 51200 bytes

__global__ void __launch_bounds__(128, 3) attn_mma()
{
    extern __shared__ __align__(16) uint32_t smw[];
    uint32_t* KsB = smw;                  // [2][64][40]
    uint32_t* VsB = KsB + 2 * KS_ST;      // [2][64][40]
    uint32_t* Ps  = VsB + 2 * KS_ST;      // [64][40]  Q staging / O packing

    const int bh = blockIdx.y;
    const int qt = gridDim.x - 1 - blockIdx.x;   // 0..31, heavy first
    const int tid = threadIdx.x;
    const int wid = tid >> 5;      // 0..3
    const int lane = tid & 31;
    const int gq = lane >> 2;
    const int tq = lane & 3;
    const int qb = qt * 64;
    const int wrow = wid * 16;

    const __half* Qp = g_q + (size_t)bh * Tn * HS;
    const __half* Kp = g_k + (size_t)bh * Tn * HS;
    const __half* Vtp = g_vt + (size_t)bh * HS * Tn;

    const uint32_t sK = (uint32_t)__cvta_generic_to_shared(KsB);
    const uint32_t sV = (uint32_t)__cvta_generic_to_shared(VsB);

    // K/Vt staging: 64 rows x 8 chunks(16B) = 512 chunks / 128 thr = 4 each
    #pragma unroll
    for (int l = 0; l < 4; l++) {
        int c = tid + l * 128;
        int rr = c >> 3;
        int ci = c & 7;
        cpa16(sK + (rr * AT_PITCH + ci * 4) * 4, Kp + (size_t)rr * HS + ci * 8);
        cpa16(sV + (rr * AT_PITCH + ci * 4) * 4, Vtp + (size_t)rr * Tn + ci * 8);
    }
    CP_COMMIT();

    // stage Q: 64 rows x 8 chunks = 512 chunks / 128 thr = 4 each
    #pragma unroll
    for (int l = 0; l < 4; l++) {
        int c = tid + l * 128;
        int rr = c >> 3;
        int ci = c & 7;
        uint4 v = *(const uint4*)(Qp + (size_t)(qb + rr) * HS + ci * 8);
        *(uint4*)&Ps[rr * AT_PITCH + ci * 4] = v;
    }
    __syncthreads();

    const int roff0 = (wrow + gq) * AT_PITCH;
    const int roff1 = (wrow + gq + 8) * AT_PITCH;

    // Q fragments via LDS.64 on pair-interleaved layout
    uint32_t qf[4][4];
    #pragma unroll
    for (int kk = 0; kk < 4; kk++) {
        uint2 l0 = *(const uint2*)&Ps[roff0 + (kk * 4 + tq) * 2];
        uint2 l1 = *(const uint2*)&Ps[roff1 + (kk * 4 + tq) * 2];
        qf[kk][0] = l0.x;
        qf[kk][2] = l0.y;
        qf[kk][1] = l1.x;
        qf[kk][3] = l1.y;
    }

    float O[8][4];
    #pragma unroll
    for (int nt = 0; nt < 8; nt++)
        #pragma unroll
        for (int r = 0; r < 4; r++) O[nt][r] = 0.f;
    float m0r = -INFINITY, m1r = -INFINITY;
    float l0r = 0.f, l1r = 0.f;

    const int ntiles = qt + 1;
    int st = 0;
    for (int kt = 0; kt < ntiles; kt++) {
        const int k0 = kt * 64;
        CP_WAIT(0);
        __syncthreads();

        if (kt + 1 < ntiles) {
            int stn = st ^ 1;
            #pragma unroll
            for (int l = 0; l < 4; l++) {
                int c = tid + l * 128;
                int rr = c >> 3;
                int ci = c & 7;
                cpa16(sK + (stn * KS_ST + rr * AT_PITCH + ci * 4) * 4,
                      Kp + (size_t)(k0 + 64 + rr) * HS + ci * 8);
                cpa16(sV + (stn * KS_ST + rr * AT_PITCH + ci * 4) * 4,
                      Vtp + (size_t)rr * Tn + k0 + 64 + ci * 8);
            }
            CP_COMMIT();
        }

        if (k0 <= qb + wrow + 15) {
            const uint32_t* Ks = KsB + st * KS_ST;
            const uint32_t* Vs = VsB + st * KS_ST;

            // ---- S = Q K^T ----
            float S[8][4];
            #pragma unroll
            for (int nt = 0; nt < 8; nt++)
                #pragma unroll
                for (int r = 0; r < 4; r++) S[nt][r] = 0.f;

            #pragma unroll
            for (int kk = 0; kk < 4; kk++) {
                #pragma unroll
                for (int nt = 0; nt < 8; nt++) {
                    uint2 b = *(const uint2*)&Ks[(nt * 8 + gq) * AT_PITCH + (kk * 4 + tq) * 2];
                    mma_f16(S[nt], qf[kk][0], qf[kk][1], qf[kk][2], qf[kk][3], b.x, b.y);
                }
            }

            // ---- causal mask (diagonal region only) ----
            if (k0 + 63 > qb + wrow) {
                int row0 = qb + wrow + gq;
                #pragma unroll
                for (int nt = 0; nt < 8; nt++) {
                    int col = k0 + nt * 8 + 2 * tq;
                    if (col     > row0)     S[nt][0] = -INFINITY;
                    if (col + 1 > row0)     S[nt][1] = -INFINITY;
                    if (col     > row0 + 8) S[nt][2] = -INFINITY;
                    if (col + 1 > row0 + 8) S[nt][3] = -INFINITY;
                }
            }

            // ---- online softmax; P packed directly into registers ----
            float cm0 = -INFINITY, cm1 = -INFINITY;
            #pragma unroll
            for (int nt = 0; nt < 8; nt++) {
                cm0 = fmaxf(cm0, fmaxf(S[nt][0], S[nt][1]));
                cm1 = fmaxf(cm1, fmaxf(S[nt][2], S[nt][3]));
            }
            cm0 = fmaxf(cm0, __shfl_xor_sync(0xffffffff, cm0, 1));
            cm0 = fmaxf(cm0, __shfl_xor_sync(0xffffffff, cm0, 2));
            cm1 = fmaxf(cm1, __shfl_xor_sync(0xffffffff, cm1, 1));
            cm1 = fmaxf(cm1, __shfl_xor_sync(0xffffffff, cm1, 2));

            float mn0 = fmaxf(m0r, cm0);
            float mn1 = fmaxf(m1r, cm1);
            bool upd = (mn0 > m0r) || (mn1 > m1r);
            if (__any_sync(0xffffffff, upd)) {
                float c0 = ex2(m0r - mn0);
                float c1 = ex2(m1r - mn1);
                l0r *= c0; l1r *= c1;
                #pragma unroll
                for (int nt = 0; nt < 8; nt++) {
                    O[nt][0] *= c0; O[nt][1] *= c0;
                    O[nt][2] *= c1; O[nt][3] *= c1;
                }
                m0r = mn0; m1r = mn1;
            }

            uint32_t Pr[8][2];
            #pragma unroll
            for (int nt = 0; nt < 8; nt++) {
                float p0 = ex2(S[nt][0] - m0r);
                float p1 = ex2(S[nt][1] - m0r);
                float p2 = ex2(S[nt][2] - m1r);
                float p3 = ex2(S[nt][3] - m1r);
                l0r += p0 + p1;
                l1r += p2 + p3;
                Pr[nt][0] = packh2(p0, p1);
                Pr[nt][1] = packh2(p2, p3);
            }

            // ---- O += P V ----
            #pragma unroll
            for (int kk = 0; kk < 4; kk++) {
                #pragma unroll
                for (int nt = 0; nt < 8; nt++) {
                    uint2 b = *(const uint2*)&Vs[(nt * 8 + gq) * AT_PITCH + (kk * 4 + tq) * 2];
                    mma_f16(O[nt], Pr[2*kk][0], Pr[2*kk][1],
                            Pr[2*kk+1][0], Pr[2*kk+1][1], b.x, b.y);
                }
            }
        }
        st ^= 1;
    }

    // ---- finalize: pack normalized O into HALF A-tiles in g_ao ----
    const int bb = bh >> 4;
    const int h = bh & 15;
    l0r += __shfl_xor_sync(0xffffffff, l0r, 1);
    l0r += __shfl_xor_sync(0xffffffff, l0r, 2);
    l1r += __shfl_xor_sync(0xffffffff, l1r, 1);
    l1r += __shfl_xor_sync(0xffffffff, l1r, 2);
    float inv0 = 1.f / l0r;
    float inv1 = 1.f / l1r;

    __syncthreads();   // all warps done reading Ps (Q)
    {
        int m0l = wrow + gq;      // 0..63 (local within block)
        int m1l = m0l + 8;
        #pragma unroll
        for (int nt = 0; nt < 8; nt++) {
            int pg = nt * 4 + tq;          // col pair 0..31 within head
            int ktl = pg >> 4;             // local k-tile (d 0..31 / 32..63)
            int pin = pg & 15;
            // offA_h(m,pin) for m in [0,64) gives words [0,1024)
            Ps[ktl * 1024 + offA_h(m0l, pin)] = packh2(O[nt][0] * inv0, O[nt][1] * inv0);
            Ps[ktl * 1024 + offA_h(m1l, pin)] = packh2(O[nt][2] * inv1, O[nt][3] * inv1);
        }
    }
    __syncthreads();
    // copy 2 half-tiles = 2048 words = 512 uint4; 4 per thread.
    // dst tile m-block = bb*16 + qt/2; half selected by qt parity.
    {
        size_t tb = ((size_t)(bb * 16 + (qt >> 1)) * 32) + h * 2;
        int par = (qt & 1) * 2048;    // halves offset within tile
        #pragma unroll
        for (int l = 0; l < 4; l++) {
            int i = tid + l * 128;    // 0..511
            int ktl = i >> 8;
            int j = i & 255;
            __half* d = g_ao + (tb + ktl) * 4096 + par + j * 8;
            *(uint4*)d = *(uint4*)&Ps[ktl * 1024 + j * 4];
        }
    }
}

// ---------------------------------------------------------------------------
extern "C" void kernel_launch(void* const* d_in, const int* in_sizes, int n_in,
                              void* d_out, int out_size)
{
    const float* x      = (const float*)d_in[0];
    const float* w_kqv  = (const float*)d_in[1];
    const float* w_proj = (const float*)d_in[2];
    const float* b_proj = (const float*)d_in[3];
    float* out = (float*)d_out;

    cudaFuncSetAttribute(attn_mma, cudaFuncAttributeMaxDynamicSharedMemorySize, SMEM_ATTN);
    cudaFuncSetAttribute(gemm_f16<0>, cudaFuncAttributeMaxDynamicSharedMemorySize, 49152);
    cudaFuncSetAttribute(gemm_f16<1>, cudaFuncAttributeMaxDynamicSharedMemorySize, 49152);

    rope_init<<<64, 1024>>>();
    {
        dim3 gp(32, 96);
        pack_all<<<gp, 256>>>(x, w_kqv, w_proj);
    }

    dim3 g1(3*Dn/128, Mrows/128);   // 24 x 64
    gemm_f16<0><<<g1, 256, 49152>>>(nullptr, nullptr);

    dim3 g2(Tn/64, Bn*Hn);          // 32 x 64
    attn_mma<<<g2, 128, SMEM_ATTN>>>();

    dim3 g3(Dn/128, Mrows/128);     // 8 x 64
    gemm_f16<1><<<g3, 256, 49152>>>(b_proj, out);
}

// round 17
// speedup vs baseline: 1.1783x; 1.0038x over previous
#include <cuda_runtime.h>
#include <cuda_fp16.h>
#include <math.h>
#include <stdint.h>

// Problem constants
#define Bn 4
#define Tn 2048
#define Dn 1024
#define Hn 16
#define HS 64
#define Mrows (Bn*Tn)          // 8192

// Scratch (device globals; no runtime allocation allowed)
// g_q/g_k: [B,H,T,64] fp16, d-dimension PAIR-INTERLEAVED per 64-half row
// g_vt:    [B,H,64,T] fp16, t-dimension PAIR-INTERLEAVED per 64-key block
__device__ __half g_q [(size_t)Bn*Hn*Tn*HS];
__device__ __half g_k [(size_t)Bn*Hn*Tn*HS];
__device__ __half g_vt[(size_t)Bn*Hn*HS*Tn];
__device__ __half g_ao[(size_t)Mrows*Dn];      // attn out, packed fp16 A-tiles
__device__ float2 g_rope[Tn*32];               // (cos, sin) table
// fragment-major packed fp16 operands: [rowblk][ktile(32-k)][4096 halves]
__device__ __half g_xt[(size_t)Mrows*Dn];
__device__ __half g_wk[(size_t)3*Dn*Dn];
__device__ __half g_wp[(size_t)Dn*Dn];

// ---------------------------------------------------------------------------
// helpers
// ---------------------------------------------------------------------------
__device__ __forceinline__ float ex2(float x) {
    float y;
    asm("ex2.approx.f32 %0, %1;" : "=f"(y) : "f"(x));
    return y;
}

__device__ __forceinline__ void mma_f16(float c[4],
                                        uint32_t a0, uint32_t a1, uint32_t a2, uint32_t a3,
                                        uint32_t b0, uint32_t b1)
{
    asm volatile(
        "mma.sync.aligned.m16n8k16.row.col.f32.f16.f16.f32 "
        "{%0,%1,%2,%3}, {%4,%5,%6,%7}, {%8,%9}, {%0,%1,%2,%3};\n"
        : "+f"(c[0]), "+f"(c[1]), "+f"(c[2]), "+f"(c[3])
        : "r"(a0), "r"(a1), "r"(a2), "r"(a3), "r"(b0), "r"(b1));
}

__device__ __forceinline__ void cpa16(uint32_t dst_smem, const void* src) {
    asm volatile("cp.async.cg.shared.global [%0], [%1], 16;" :: "r"(dst_smem), "l"(src));
}
#define CP_COMMIT()  asm volatile("cp.async.commit_group;")
#define CP_WAIT(n)   asm volatile("cp.async.wait_group " #n ";")

__device__ __forceinline__ uint32_t packh2(float a, float b) {
    __half2 h = __floats2half2_rn(a, b);
    return *(uint32_t*)&h;
}

// pair-interleave permutation on 32-word blocks: word w=8kk+r ->
//   pos = (4kk+r)*2 if r<4 else (4kk+r-4)*2+1
__device__ __forceinline__ int permw(int w) {
    int kk = w >> 3;
    int r = w & 7;
    return (r < 4) ? (kk * 4 + r) * 2 : (kk * 4 + r - 4) * 2 + 1;
}

// word offset within a 128x32 fp16 tile (2048 words), p = k-pair 0..15
__device__ __forceinline__ int offA_h(int m, int p) {
    return (((((m >> 4) * 2 + (p >> 3)) * 8 + (m & 7)) * 4 + (p & 3)) * 4)
           + ((p >> 2) & 1) * 2 + ((m >> 3) & 1);
}
__device__ __forceinline__ int offB_h(int n, int p) {
    return (((((n >> 3) * 2 + (p >> 3)) * 8 + (n & 7)) * 4 + (p & 3)) * 2)
           + ((p >> 2) & 1);
}

// ---------------------------------------------------------------------------
// Pack ALL THREE operands + build the RoPE table in ONE launch.
// grid = (32, 104): by 0-63 x->g_xt (A), 64-87 w_kqv->g_wk (B),
// 88-95 w_proj->g_wp (B), 96-103 rope table (one entry per thread).
// ---------------------------------------------------------------------------
__global__ void __launch_bounds__(256) pack_all(const float* __restrict__ x,
                                                const float* __restrict__ wk,
                                                const float* __restrict__ wp)
{
    __shared__ __align__(16) __half sm[4096];
    const int by = blockIdx.y;
    const int tid = threadIdx.x;

    if (by >= 96) {
        // rope: 8 by-blocks x 32 bx-blocks x 256 threads = 65536 entries
        int idx = ((by - 96) * 32 + blockIdx.x) * 256 + tid;
        int t = idx >> 5;
        int i = idx & 31;
        float theta = powf(10000.0f, (float)i * (-2.0f / 64.0f));
        float ang = (float)t * theta;
        float sn, cs;
        sincosf(ang, &sn, &cs);
        g_rope[idx] = make_float2(cs, sn);
        return;
    }

    int sel, mblk;
    const float* src;
    if (by < 64)      { sel = 0; mblk = by;      src = x;  }
    else if (by < 88) { sel = 1; mblk = by - 64; src = wk; }
    else              { sel = 2; mblk = by - 88; src = wp; }
    __half* dst = (sel == 0) ? g_xt : (sel == 1) ? g_wk : g_wp;
    const bool isA = (sel == 0);

    const int k0 = blockIdx.x * 32;
    const int m0 = mblk * 128;

    #pragma unroll
    for (int l = 0; l < 4; l++) {
        int idx = tid + l * 256;
        int row = idx >> 3;
        int c4 = (idx & 7) * 4;
        float4 v = *(const float4*)(src + (size_t)(m0 + row) * 1024 + k0 + c4);
        int p = c4 >> 1;
        __half2 w0 = __floats2half2_rn(v.x, v.y);
        __half2 w1 = __floats2half2_rn(v.z, v.w);
        int o0 = isA ? offA_h(row, p)     : offB_h(row, p);
        int o1 = isA ? offA_h(row, p + 1) : offB_h(row, p + 1);
        *(__half2*)&sm[o0 * 2] = w0;
        *(__half2*)&sm[o1 * 2] = w1;
    }
    __syncthreads();
    size_t gb = ((size_t)mblk * 32 + blockIdx.x) * 4096;
    #pragma unroll
    for (int l = 0; l < 2; l++) {
        int i = tid + l * 256;
        *(uint4*)&dst[gb + (size_t)i * 8] = *(uint4*)&sm[i * 8];
    }
}

// ---------------------------------------------------------------------------
// fp16 tensor-core GEMM on PACKED operands: C[M,N] = A @ W^T, K=1024.
// MODE 0: QKV epilogue writes PAIR-INTERLEAVED g_q/g_k/g_vt.
// MODE 1: proj epilogue (bias -> out), A = g_ao.
// ---------------------------------------------------------------------------
template<int MODE>
__global__ void __launch_bounds__(256) gemm_f16(const float* __restrict__ bias,
                                                float* __restrict__ out)
{
    extern __shared__ __align__(16) uint32_t gsm[];
    uint32_t* As = gsm;            // [3][2048 words]
    uint32_t* Ws = gsm + 3 * 2048;

    const int m0 = blockIdx.y * 128;
    const int n0 = blockIdx.x * 128;
    const int tid = threadIdx.x;
    const int wid = tid >> 5;
    const int lane = tid & 31;
    const int wm = wid >> 2;
    const int wn = wid & 3;
    const int gq = lane >> 2;
    const int tq = lane & 3;

    const __half* Abase = (MODE == 1) ? g_ao : g_xt;
    const __half* Wbase = (MODE == 1) ? g_wp : g_wk;
    const __half* Atiles = Abase + (size_t)blockIdx.y * 32 * 4096;
    const __half* Wtiles = Wbase + (size_t)blockIdx.x * 32 * 4096;

    const uint32_t sA = (uint32_t)__cvta_generic_to_shared(As);
    const uint32_t sW = (uint32_t)__cvta_generic_to_shared(Ws);

    float acc[4][4][4];
    #pragma unroll
    for (int mt = 0; mt < 4; mt++)
        #pragma unroll
        for (int nt = 0; nt < 4; nt++)
            #pragma unroll
            for (int r = 0; r < 4; r++) acc[mt][nt][r] = 0.f;

    #pragma unroll
    for (int p = 0; p < 2; p++) {
        cpa16(sA + (p * 2048 + tid * 8 + 0) * 4, Atiles + (size_t)p * 4096 + tid * 16 + 0);
        cpa16(sA + (p * 2048 + tid * 8 + 4) * 4, Atiles + (size_t)p * 4096 + tid * 16 + 8);
        cpa16(sW + (p * 2048 + tid * 8 + 0) * 4, Wtiles + (size_t)p * 4096 + tid * 16 + 0);
        cpa16(sW + (p * 2048 + tid * 8 + 4) * 4, Wtiles + (size_t)p * 4096 + tid * 16 + 8);
        CP_COMMIT();
    }

    int st = 0;
    for (int kt = 0; kt < 32; kt++) {
        if (kt < 31) { CP_WAIT(1); } else { CP_WAIT(0); }
        __syncthreads();

        if (kt + 2 < 32) {
            int stn = st + 2; if (stn >= 3) stn -= 3;
            const __half* At = Atiles + (size_t)(kt + 2) * 4096;
            const __half* Wt = Wtiles + (size_t)(kt + 2) * 4096;
            cpa16(sA + (stn * 2048 + tid * 8 + 0) * 4, At + tid * 16 + 0);
            cpa16(sA + (stn * 2048 + tid * 8 + 4) * 4, At + tid * 16 + 8);
            cpa16(sW + (stn * 2048 + tid * 8 + 0) * 4, Wt + tid * 16 + 0);
            cpa16(sW + (stn * 2048 + tid * 8 + 4) * 4, Wt + tid * 16 + 8);
            CP_COMMIT();
        }

        const uint32_t* Acur = As + st * 2048;
        const uint32_t* Wcur = Ws + st * 2048;
        #pragma unroll
        for (int ks = 0; ks < 2; ks++) {
            uint4 af[4];
            uint2 bf[4];
            #pragma unroll
            for (int mt = 0; mt < 4; mt++)
                af[mt] = *(const uint4*)&Acur[((((wm * 4 + mt) * 2 + ks) * 8 + gq) * 4 + tq) * 4];
            #pragma unroll
            for (int nt = 0; nt < 4; nt++)
                bf[nt] = *(const uint2*)&Wcur[((((wn * 4 + nt) * 2 + ks) * 8 + gq) * 4 + tq) * 2];
            #pragma unroll
            for (int mt = 0; mt < 4; mt++)
                #pragma unroll
                for (int nt = 0; nt < 4; nt++)
                    mma_f16(acc[mt][nt], af[mt].x, af[mt].y, af[mt].z, af[mt].w,
                            bf[nt].x, bf[nt].y);
        }
        st = (st == 2) ? 0 : st + 1;
    }

    if (MODE == 0) {
        const float QSC = 0.125f * 1.4426950408889634f;  // scale * log2(e)
        #pragma unroll
        for (int mt = 0; mt < 4; mt++) {
            #pragma unroll
            for (int r = 0; r < 2; r++) {
                int m = m0 + wm * 64 + mt * 16 + gq + r * 8;
                int bb = m >> 11;
                int tt = m & 2047;
                #pragma unroll
                for (int nt = 0; nt < 4; nt++) {
                    int col = n0 + wn * 32 + nt * 8 + 2 * tq;
                    int which = col >> 10;
                    int rem = col & 1023;
                    int h = rem >> 6;
                    int d = rem & 63;        // even
                    int bh = bb * Hn + h;
                    float e = acc[mt][nt][r * 2 + 0];
                    float o = acc[mt][nt][r * 2 + 1];
                    if (which == 2) {
                        int u = tt & 63;
                        int colp = (tt & ~63) + 2 * permw(u >> 1) + (u & 1);
                        size_t vo = ((size_t)bh * HS + d) * Tn + colp;
                        g_vt[vo]      = __float2half_rn(e);
                        g_vt[vo + Tn] = __float2half_rn(o);
                    } else {
                        float2 cs = g_rope[tt * 32 + (d >> 1)];
                        float t1 = e * cs.x - o * cs.y;
                        float t2 = e * cs.y + o * cs.x;
                        size_t off = ((size_t)bh * Tn + tt) * HS + 2 * permw(d >> 1);
                        if (which == 0) {
                            *(__half2*)(g_k + off) = __floats2half2_rn(t1, t2);
                        } else {
                            *(__half2*)(g_q + off) = __floats2half2_rn(t1 * QSC, t2 * QSC);
                        }
                    }
                }
            }
        }
    } else {
        #pragma unroll
        for (int mt = 0; mt < 4; mt++) {
            #pragma unroll
            for (int r = 0; r < 2; r++) {
                int m = m0 + wm * 64 + mt * 16 + gq + r * 8;
                #pragma unroll
                for (int nt = 0; nt < 4; nt++) {
                    int col = n0 + wn * 32 + nt * 8 + 2 * tq;
                    float2 v2;
                    v2.x = acc[mt][nt][r * 2 + 0] + bias[col + 0];
                    v2.y = acc[mt][nt][r * 2 + 1] + bias[col + 1];
                    *(float2*)(out + (size_t)m * 1024 + col) = v2;
                }
            }
        }
    }
}

// ---------------------------------------------------------------------------
// fp16 tensor-core causal flash attention (mma m16n8k16), m32 warp tiles,
// 2 CTAs/SM. ONES-ROW TRICK: Vt smem has 8 extra rows of 1.0 (rows 64-71);
// the PV MMA with nt=8 computes the softmax denominator l = P @ 1 inside the
// tensor core (O[8][0]=O[8][1]=l0, O[8][2]=O[8][3]=l1, quad-replicated) —
// no scalar l accumulation, no final shuffle reduce.
// Pair-interleaved operands -> LDS.64 fragments; P in registers.
// grid = (16, 64); heavy q-blocks first. smem pitch 40 words.
// ---------------------------------------------------------------------------
#define AT_PITCH 40                       // words per 64-half row
#define KS_ST (64*AT_PITCH)               // 2560 words per K stage
#define VS_ST (72*AT_PITCH)               // 2880 words per V stage (64 + 8 ones)
#define SMEM_ATTN ((2*KS_ST + 2*VS_ST + 128*AT_PITCH) * 4)   // 64000 bytes

__global__ void __launch_bounds__(128, 2) attn_mma()
{
    extern __shared__ __align__(16) uint32_t smw[];
    uint32_t* KsB = smw;                  // [2][64][40]
    uint32_t* VsB = KsB + 2 * KS_ST;      // [2][72][40] (rows 64-71 = ones)
    uint32_t* Ps  = VsB + 2 * VS_ST;      // [128][40]  Q staging / O packing

    const int bh = blockIdx.y;
    const int qt = gridDim.x - 1 - blockIdx.x;   // heavy blocks first
    const int tid = threadIdx.x;
    const int wid = tid >> 5;
    const int lane = tid & 31;
    const int gq = lane >> 2;
    const int tq = lane & 3;
    const int qb = qt * 128;
    const int wrow = wid * 32;

    const __half* Qp = g_q + (size_t)bh * Tn * HS;
    const __half* Kp = g_k + (size_t)bh * Tn * HS;
    const __half* Vtp = g_vt + (size_t)bh * HS * Tn;

    const uint32_t sK = (uint32_t)__cvta_generic_to_shared(KsB);
    const uint32_t sV = (uint32_t)__cvta_generic_to_shared(VsB);

    // K/Vt staging (rows 0..63): 512 chunks / 128 thr = 4 each
    #pragma unroll
    for (int l = 0; l < 4; l++) {
        int c = tid + l * 128;
        int rr = c >> 3;
        int ci = c & 7;
        cpa16(sK + (rr * AT_PITCH + ci * 4) * 4, Kp + (size_t)rr * HS + ci * 8);
        cpa16(sV + (rr * AT_PITCH + ci * 4) * 4, Vtp + (size_t)rr * Tn + ci * 8);
    }
    CP_COMMIT();

    // ones rows (64..71) for BOTH V stages: 2*8 rows x 32 words = 512 / 128 = 4
    #pragma unroll
    for (int l = 0; l < 4; l++) {
        int c = tid + l * 128;            // 0..511
        int stg = c >> 8;                 // 0..1
        int rr = 64 + ((c >> 5) & 7);     // 64..71
        int cw = c & 31;                  // word 0..31
        VsB[stg * VS_ST + rr * AT_PITCH + cw] = 0x3C003C00u;  // (1.0h, 1.0h)
    }

    // stage Q tile into Ps (128 rows x 8 chunks)
    #pragma unroll
    for (int l = 0; l < 8; l++) {
        int c = tid + l * 128;
        int rr = c >> 3;
        int ci = c & 7;
        uint4 v = *(const uint4*)(Qp + (size_t)(qb + rr) * HS + ci * 8);
        *(uint4*)&Ps[rr * AT_PITCH + ci * 4] = v;
    }
    __syncthreads();

    int roff[2][2];
    #pragma unroll
    for (int s = 0; s < 2; s++) {
        roff[s][0] = (wrow + 16 * s + gq) * AT_PITCH;
        roff[s][1] = (wrow + 16 * s + gq + 8) * AT_PITCH;
    }

    // Q fragments via LDS.64 on pair-interleaved layout
    uint32_t qf[2][4][4];
    #pragma unroll
    for (int s = 0; s < 2; s++)
        #pragma unroll
        for (int kk = 0; kk < 4; kk++) {
            uint2 l0 = *(const uint2*)&Ps[roff[s][0] + (kk * 4 + tq) * 2];
            uint2 l1 = *(const uint2*)&Ps[roff[s][1] + (kk * 4 + tq) * 2];
            qf[s][kk][0] = l0.x;
            qf[s][kk][2] = l0.y;
            qf[s][kk][1] = l1.x;
            qf[s][kk][3] = l1.y;
        }

    // O[.][8] holds the denominator accumulators (ones column)
    float O[2][9][4];
    #pragma unroll
    for (int s = 0; s < 2; s++)
        #pragma unroll
        for (int nt = 0; nt < 9; nt++)
            #pragma unroll
            for (int r = 0; r < 4; r++) O[s][nt][r] = 0.f;
    float mrow[2][2];
    #pragma unroll
    for (int s = 0; s < 2; s++) { mrow[s][0] = -INFINITY; mrow[s][1] = -INFINITY; }

    const int ntiles = 2 * qt + 2;
    int st = 0;
    for (int kt = 0; kt < ntiles; kt++) {
        const int k0 = kt * 64;
        CP_WAIT(0);
        __syncthreads();

        if (kt + 1 < ntiles) {
            int stn = st ^ 1;
            #pragma unroll
            for (int l = 0; l < 4; l++) {
                int c = tid + l * 128;
                int rr = c >> 3;
                int ci = c & 7;
                cpa16(sK + (stn * KS_ST + rr * AT_PITCH + ci * 4) * 4,
                      Kp + (size_t)(k0 + 64 + rr) * HS + ci * 8);
                cpa16(sV + (stn * VS_ST + rr * AT_PITCH + ci * 4) * 4,
                      Vtp + (size_t)rr * Tn + k0 + 64 + ci * 8);
            }
            CP_COMMIT();
        }

        if (k0 <= qb + wrow + 31) {
            const uint32_t* Ks = KsB + st * KS_ST;
            const uint32_t* Vs = VsB + st * VS_ST;

            // ---- S = Q K^T ---- (B frag = one LDS.64)
            float S[2][8][4];
            #pragma unroll
            for (int s = 0; s < 2; s++)
                #pragma unroll
                for (int nt = 0; nt < 8; nt++)
                    #pragma unroll
                    for (int r = 0; r < 4; r++) S[s][nt][r] = 0.f;

            #pragma unroll
            for (int kk = 0; kk < 4; kk++) {
                #pragma unroll
                for (int nt = 0; nt < 8; nt++) {
                    uint2 b = *(const uint2*)&Ks[(nt * 8 + gq) * AT_PITCH + (kk * 4 + tq) * 2];
                    mma_f16(S[0][nt], qf[0][kk][0], qf[0][kk][1], qf[0][kk][2], qf[0][kk][3], b.x, b.y);
                    mma_f16(S[1][nt], qf[1][kk][0], qf[1][kk][1], qf[1][kk][2], qf[1][kk][3], b.x, b.y);
                }
            }

            // ---- causal mask ----
            if (k0 + 63 > qb + wrow) {
                #pragma unroll
                for (int s = 0; s < 2; s++) {
                    int row0 = qb + wrow + 16 * s + gq;
                    #pragma unroll
                    for (int nt = 0; nt < 8; nt++) {
                        int col = k0 + nt * 8 + 2 * tq;
                        if (col     > row0)     S[s][nt][0] = -INFINITY;
                        if (col + 1 > row0)     S[s][nt][1] = -INFINITY;
                        if (col     > row0 + 8) S[s][nt][2] = -INFINITY;
                        if (col + 1 > row0 + 8) S[s][nt][3] = -INFINITY;
                    }
                }
            }

            // ---- online softmax; P packed directly into registers ----
            uint32_t Pr[2][8][2];
            #pragma unroll
            for (int s = 0; s < 2; s++) {
                float cm0 = -INFINITY, cm1 = -INFINITY;
                #pragma unroll
                for (int nt = 0; nt < 8; nt++) {
                    cm0 = fmaxf(cm0, fmaxf(S[s][nt][0], S[s][nt][1]));
                    cm1 = fmaxf(cm1, fmaxf(S[s][nt][2], S[s][nt][3]));
                }
                cm0 = fmaxf(cm0, __shfl_xor_sync(0xffffffff, cm0, 1));
                cm0 = fmaxf(cm0, __shfl_xor_sync(0xffffffff, cm0, 2));
                cm1 = fmaxf(cm1, __shfl_xor_sync(0xffffffff, cm1, 1));
                cm1 = fmaxf(cm1, __shfl_xor_sync(0xffffffff, cm1, 2));

                float mn0 = fmaxf(mrow[s][0], cm0);
                float mn1 = fmaxf(mrow[s][1], cm1);
                bool upd = (mn0 > mrow[s][0]) || (mn1 > mrow[s][1]);
                if (__any_sync(0xffffffff, upd)) {
                    float c0 = ex2(mrow[s][0] - mn0);
                    float c1 = ex2(mrow[s][1] - mn1);
                    #pragma unroll
                    for (int nt = 0; nt < 9; nt++) {   // includes denominator col
                        O[s][nt][0] *= c0; O[s][nt][1] *= c0;
                        O[s][nt][2] *= c1; O[s][nt][3] *= c1;
                    }
                    mrow[s][0] = mn0; mrow[s][1] = mn1;
                }

                #pragma unroll
                for (int nt = 0; nt < 8; nt++) {
                    float p0 = ex2(S[s][nt][0] - mrow[s][0]);
                    float p1 = ex2(S[s][nt][1] - mrow[s][0]);
                    float p2 = ex2(S[s][nt][2] - mrow[s][1]);
                    float p3 = ex2(S[s][nt][3] - mrow[s][1]);
                    Pr[s][nt][0] = packh2(p0, p1);
                    Pr[s][nt][1] = packh2(p2, p3);
                }
            }

            // ---- O += P [V | 1] ---- (nt=8 column accumulates l)
            #pragma unroll
            for (int kk = 0; kk < 4; kk++) {
                #pragma unroll
                for (int nt = 0; nt < 9; nt++) {
                    uint2 b = *(const uint2*)&Vs[(nt * 8 + gq) * AT_PITCH + (kk * 4 + tq) * 2];
                    mma_f16(O[0][nt], Pr[0][2*kk][0], Pr[0][2*kk][1],
                            Pr[0][2*kk+1][0], Pr[0][2*kk+1][1], b.x, b.y);
                    mma_f16(O[1][nt], Pr[1][2*kk][0], Pr[1][2*kk][1],
                            Pr[1][2*kk+1][0], Pr[1][2*kk+1][1], b.x, b.y);
                }
            }
        }
        st ^= 1;
    }

    // ---- finalize: l comes from O[.][8] (quad-replicated); pack A-tiles ----
    const int bb = bh >> 4;
    const int h = bh & 15;
    __syncthreads();
    #pragma unroll
    for (int s = 0; s < 2; s++) {
        float inv0 = 1.f / O[s][8][0];
        float inv1 = 1.f / O[s][8][2];
        int m0l = wrow + 16 * s + gq;
        int m1l = m0l + 8;
        #pragma unroll
        for (int nt = 0; nt < 8; nt++) {
            int pg = nt * 4 + tq;
            int ktl = pg >> 4;
            int pin = pg & 15;
            Ps[ktl * 2048 + offA_h(m0l, pin)] = packh2(O[s][nt][0] * inv0, O[s][nt][1] * inv0);
            Ps[ktl * 2048 + offA_h(m1l, pin)] = packh2(O[s][nt][2] * inv1, O[s][nt][3] * inv1);
        }
    }
    __syncthreads();
    {
        __half* dst = g_ao + (((size_t)(bb * 16 + qt) * 32) + h * 2) * 4096;
        #pragma unroll
        for (int l = 0; l < 8; l++) {
            int i = tid + l * 128;
            *(uint4*)&dst[(size_t)i * 8] = *(uint4*)&Ps[i * 4];
        }
    }
}

// ---------------------------------------------------------------------------
extern "C" void kernel_launch(void* const* d_in, const int* in_sizes, int n_in,
                              void* d_out, int out_size)
{
    const float* x      = (const float*)d_in[0];
    const float* w_kqv  = (const float*)d_in[1];
    const float* w_proj = (const float*)d_in[2];
    const float* b_proj = (const float*)d_in[3];
    float* out = (float*)d_out;

    cudaFuncSetAttribute(attn_mma, cudaFuncAttributeMaxDynamicSharedMemorySize, SMEM_ATTN);
    cudaFuncSetAttribute(gemm_f16<0>, cudaFuncAttributeMaxDynamicSharedMemorySize, 49152);
    cudaFuncSetAttribute(gemm_f16<1>, cudaFuncAttributeMaxDynamicSharedMemorySize, 49152);

    {
        dim3 gp(32, 104);            // packs + rope table fused
        pack_all<<<gp, 256>>>(x, w_kqv, w_proj);
    }

    dim3 g1(3*Dn/128, Mrows/128);   // 24 x 64
    gemm_f16<0><<<g1, 256, 49152>>>(nullptr, nullptr);

    dim3 g2(Tn/128, Bn*Hn);         // 16 x 64
    attn_mma<<<g2, 128, SMEM_ATTN>>>();

    dim3 g3(Dn/128, Mrows/128);     // 8 x 64
    gemm_f16<1><<<g3, 256, 49152>>>(b_proj, out);
}